// round 1
// baseline (speedup 1.0000x reference)
#include <cuda_runtime.h>

#define DM   1024
#define NH   16
#define DH   64
#define SQ   2048
#define BB   2
#define MR   (BB*SQ)      // 4096 token rows
#define N3   (3*DM)       // 3072
#define RANK 8
#define NEGBIG (-1.25e8f) // -1e9 / sqrt(64)

// ---------------- scratch (static __device__, no allocations) ----------------
__device__ float g_Weff[(size_t)DM * N3];   // 12 MB folded QKV weight
__device__ float g_Ceff[(size_t)DM * DM];   //  4 MB folded proj weight
__device__ float g_qkv [(size_t)MR * N3];   // 48 MB qkv activations
__device__ float g_ctx [(size_t)MR * DM];   // 16 MB attention output

// ---------------- LoRA fold: out = W + 2 * (A @ B) ----------------
__global__ void fold_lora_kernel(const float* __restrict__ W,
                                 const float* __restrict__ A,
                                 const float* __restrict__ Bm,
                                 float* __restrict__ out, int N, int total)
{
    int idx = blockIdx.x * 256 + threadIdx.x;
    if (idx >= total) return;
    int k = idx / N, n = idx - k * N;
    float s = 0.f;
#pragma unroll
    for (int r = 0; r < RANK; ++r)
        s = fmaf(A[k * RANK + r], Bm[r * N + n], s);
    out[idx] = W[idx] + 2.0f * s;
}

// ---------------- 128x128x16 fp32 GEMM, C = A(MxK) * B(KxN) + bias ----------------
__global__ __launch_bounds__(256) void sgemm_bias_kernel(
    const float* __restrict__ A, const float* __restrict__ B,
    const float* __restrict__ bias, float* __restrict__ C,
    int M, int N, int K)
{
    __shared__ float As[16][128];
    __shared__ float Bs[16][128];
    const int tid = threadIdx.x;
    const int tx = tid & 15, ty = tid >> 4;
    const int row0 = blockIdx.y * 128, col0 = blockIdx.x * 128;

    const int ar = tid >> 1;            // 0..127 (A tile row)
    const int ak = (tid & 1) * 8;       // 0 or 8 (A tile k offset)
    const int br = tid >> 4;            // 0..15  (B tile k row)
    const int bc = (tid & 15) * 8;      // B tile col offset

    float acc[8][8] = {};

    for (int k0 = 0; k0 < K; k0 += 16) {
        float4 a0 = *(const float4*)&A[(size_t)(row0 + ar) * K + k0 + ak];
        float4 a1 = *(const float4*)&A[(size_t)(row0 + ar) * K + k0 + ak + 4];
        As[ak + 0][ar] = a0.x; As[ak + 1][ar] = a0.y;
        As[ak + 2][ar] = a0.z; As[ak + 3][ar] = a0.w;
        As[ak + 4][ar] = a1.x; As[ak + 5][ar] = a1.y;
        As[ak + 6][ar] = a1.z; As[ak + 7][ar] = a1.w;
        float4 b0 = *(const float4*)&B[(size_t)(k0 + br) * N + col0 + bc];
        float4 b1 = *(const float4*)&B[(size_t)(k0 + br) * N + col0 + bc + 4];
        *(float4*)&Bs[br][bc]     = b0;
        *(float4*)&Bs[br][bc + 4] = b1;
        __syncthreads();
#pragma unroll
        for (int kk = 0; kk < 16; ++kk) {
            float a[8], b[8];
#pragma unroll
            for (int i = 0; i < 8; ++i) a[i] = As[kk][ty * 8 + i];
#pragma unroll
            for (int j = 0; j < 8; ++j) b[j] = Bs[kk][tx * 8 + j];
#pragma unroll
            for (int i = 0; i < 8; ++i)
#pragma unroll
                for (int j = 0; j < 8; ++j)
                    acc[i][j] = fmaf(a[i], b[j], acc[i][j]);
        }
        __syncthreads();
    }

#pragma unroll
    for (int i = 0; i < 8; ++i) {
        int r = row0 + ty * 8 + i;
#pragma unroll
        for (int j = 0; j < 8; j += 4) {
            int c = col0 + tx * 8 + j;
            float4 o;
            o.x = acc[i][j + 0] + bias[c + 0];
            o.y = acc[i][j + 1] + bias[c + 1];
            o.z = acc[i][j + 2] + bias[c + 2];
            o.w = acc[i][j + 3] + bias[c + 3];
            *(float4*)&C[(size_t)r * N + c] = o;
        }
    }
}

// ---------------- flash attention: BM=BN=64, Dh=64, fp32 online softmax ----------------
// grid: (S/64, NH, BB); 256 threads (16x16 micro-tiling, 4x4 per thread)
#define FST 65  // smem row stride (pad to kill 64-stride bank conflicts)
#define FLASH_SMEM ((4*64*FST + 3*64) * 4 + 64 * 4)

__global__ __launch_bounds__(256) void flash_kernel(const int* __restrict__ amask)
{
    extern __shared__ float sm[];
    float* q_s = sm;                   // 64 x FST
    float* k_s = q_s + 64 * FST;
    float* v_s = k_s + 64 * FST;
    float* p_s = v_s + 64 * FST;       // scores / probs
    float* m_s = p_s + 64 * FST;       // running max  [64]
    float* l_s = m_s + 64;             // running sum  [64]
    float* a_s = l_s + 64;             // alpha        [64]
    int*   msk = (int*)(a_s + 64);     // pad mask     [64]

    const int qt = blockIdx.x, h = blockIdx.y, b = blockIdx.z;
    const int tid = threadIdx.x;
    const int tx = tid & 15, ty = tid >> 4;
    const int wid = tid >> 5, lane = tid & 31;
    const int q0 = qt * 64;

    // load Q tile (64 rows x 64 d), coalesced float4
    for (int i = tid; i < 64 * 16; i += 256) {
        int r = i >> 4, c4 = (i & 15) << 2;
        float4 v = *(const float4*)&g_qkv[(size_t)(b * SQ + q0 + r) * N3 + h * DH + c4];
        q_s[r * FST + c4 + 0] = v.x; q_s[r * FST + c4 + 1] = v.y;
        q_s[r * FST + c4 + 2] = v.z; q_s[r * FST + c4 + 3] = v.w;
    }
    if (tid < 64) { m_s[tid] = -1e30f; l_s[tid] = 0.f; }

    float o[4][4] = {};

    for (int kt = 0; kt <= qt; ++kt) {
        __syncthreads();  // previous iteration's k_s/v_s/p_s reads done (also covers Q load)
        const int kb = kt * 64;
        for (int i = tid; i < 64 * 16; i += 256) {
            int r = i >> 4, c4 = (i & 15) << 2;
            size_t g = (size_t)(b * SQ + kb + r) * N3 + DM + h * DH + c4;
            float4 kv = *(const float4*)&g_qkv[g];
            float4 vv = *(const float4*)&g_qkv[g + DM];
            k_s[r * FST + c4 + 0] = kv.x; k_s[r * FST + c4 + 1] = kv.y;
            k_s[r * FST + c4 + 2] = kv.z; k_s[r * FST + c4 + 3] = kv.w;
            v_s[r * FST + c4 + 0] = vv.x; v_s[r * FST + c4 + 1] = vv.y;
            v_s[r * FST + c4 + 2] = vv.z; v_s[r * FST + c4 + 3] = vv.w;
        }
        if (tid < 64) msk[tid] = amask[b * SQ + kb + tid];
        __syncthreads();

        // S = Q K^T  (4x4 micro-tile per thread)
        float sa[4][4] = {};
#pragma unroll 4
        for (int d = 0; d < 64; ++d) {
            float qa[4], kv[4];
#pragma unroll
            for (int i = 0; i < 4; ++i) qa[i] = q_s[(ty * 4 + i) * FST + d];
#pragma unroll
            for (int j = 0; j < 4; ++j) kv[j] = k_s[(tx * 4 + j) * FST + d];
#pragma unroll
            for (int i = 0; i < 4; ++i)
#pragma unroll
                for (int j = 0; j < 4; ++j)
                    sa[i][j] = fmaf(qa[i], kv[j], sa[i][j]);
        }
        // mask (causal + pad) BEFORE scale (matches reference: -1e9 scaled too)
#pragma unroll
        for (int i = 0; i < 4; ++i) {
            const int rg = q0 + ty * 4 + i;
#pragma unroll
            for (int j = 0; j < 4; ++j) {
                const int cj = tx * 4 + j;
                const int cg = kb + cj;
                float sv = (cg > rg || msk[cj] == 0) ? NEGBIG : sa[i][j] * 0.125f;
                p_s[(ty * 4 + i) * FST + cj] = sv;
            }
        }
        __syncthreads();

        // online softmax: warp w owns rows w*8 .. w*8+7
#pragma unroll
        for (int rr = 0; rr < 8; ++rr) {
            const int r = wid * 8 + rr;
            float s0 = p_s[r * FST + lane];
            float s1 = p_s[r * FST + 32 + lane];
            float mx = fmaxf(s0, s1);
#pragma unroll
            for (int off = 16; off; off >>= 1)
                mx = fmaxf(mx, __shfl_xor_sync(0xffffffffu, mx, off));
            float mold = m_s[r];
            float mnew = fmaxf(mold, mx);
            float p0 = __expf(s0 - mnew);
            float p1 = __expf(s1 - mnew);
            p_s[r * FST + lane]      = p0;
            p_s[r * FST + 32 + lane] = p1;
            float sum = p0 + p1;
#pragma unroll
            for (int off = 16; off; off >>= 1)
                sum += __shfl_xor_sync(0xffffffffu, sum, off);
            if (lane == 0) {
                float al = __expf(mold - mnew);
                a_s[r] = al;
                l_s[r] = l_s[r] * al + sum;
                m_s[r] = mnew;
            }
        }
        __syncthreads();

        // O = O*alpha + P V
        float al[4];
#pragma unroll
        for (int i = 0; i < 4; ++i) al[i] = a_s[ty * 4 + i];
#pragma unroll
        for (int i = 0; i < 4; ++i)
#pragma unroll
            for (int j = 0; j < 4; ++j) o[i][j] *= al[i];

#pragma unroll 4
        for (int kk = 0; kk < 64; ++kk) {
            float pv[4], vv[4];
#pragma unroll
            for (int i = 0; i < 4; ++i) pv[i] = p_s[(ty * 4 + i) * FST + kk];
#pragma unroll
            for (int j = 0; j < 4; ++j) vv[j] = v_s[kk * FST + tx * 4 + j];
#pragma unroll
            for (int i = 0; i < 4; ++i)
#pragma unroll
                for (int j = 0; j < 4; ++j)
                    o[i][j] = fmaf(pv[i], vv[j], o[i][j]);
        }
    }

    // epilogue: ctx[b, s, h*64+d] = O / l   (l_s ordered by last in-loop barrier)
#pragma unroll
    for (int i = 0; i < 4; ++i) {
        const int rg = q0 + ty * 4 + i;
        const float inv = 1.0f / l_s[ty * 4 + i];
#pragma unroll
        for (int j = 0; j < 4; ++j)
            g_ctx[(size_t)(b * SQ + rg) * DM + h * DH + tx * 4 + j] = o[i][j] * inv;
    }
}

// ---------------- launch ----------------
extern "C" void kernel_launch(void* const* d_in, const int* in_sizes, int n_in,
                              void* d_out, int out_size)
{
    const float* x     = (const float*)d_in[0];
    const int*   amask = (const int*)  d_in[1];
    const float* Wqkv  = (const float*)d_in[2];
    const float* bqkv  = (const float*)d_in[3];
    const float* Aqkv  = (const float*)d_in[4];
    const float* Bqkv  = (const float*)d_in[5];
    const float* Wproj = (const float*)d_in[6];
    const float* bproj = (const float*)d_in[7];
    const float* Aproj = (const float*)d_in[8];
    const float* Bproj = (const float*)d_in[9];
    float* out = (float*)d_out;

    float *weff, *ceff, *qkv, *ctx;
    cudaGetSymbolAddress((void**)&weff, g_Weff);
    cudaGetSymbolAddress((void**)&ceff, g_Ceff);
    cudaGetSymbolAddress((void**)&qkv,  g_qkv);
    cudaGetSymbolAddress((void**)&ctx,  g_ctx);

    // fold LoRA into weights: W_eff = W + 2*(A@B)
    fold_lora_kernel<<<(DM * N3 + 255) / 256, 256>>>(Wqkv,  Aqkv,  Bqkv,  weff, N3, DM * N3);
    fold_lora_kernel<<<(DM * DM + 255) / 256, 256>>>(Wproj, Aproj, Bproj, ceff, DM, DM * DM);

    // qkv = x @ W_eff + bias
    sgemm_bias_kernel<<<dim3(N3 / 128, MR / 128), 256>>>(x, weff, bqkv, qkv, MR, N3, DM);

    // flash attention -> ctx
    cudaFuncSetAttribute(flash_kernel, cudaFuncAttributeMaxDynamicSharedMemorySize, FLASH_SMEM);
    flash_kernel<<<dim3(SQ / 64, NH, BB), 256, FLASH_SMEM>>>(amask);

    // out = ctx @ C_eff + bias
    sgemm_bias_kernel<<<dim3(DM / 128, MR / 128), 256>>>(ctx, ceff, bproj, out, MR, DM, DM);
}

// round 3
// speedup vs baseline: 1.3529x; 1.3529x over previous
#include <cuda_runtime.h>
#include <cuda_bf16.h>
#include <cstdint>

#define DM   1024
#define NH   16
#define DH   64
#define SQ   2048
#define BB   2
#define MR   (BB*SQ)      // 4096 token rows
#define N3   (3*DM)       // 3072
#define RANK 8
#define NEGBIG (-1.25e8f) // -1e9 / sqrt(64)

// ---------------- scratch (static __device__, no allocations) ----------------
__device__ float g_qkv [(size_t)MR * N3];   // 48 MB qkv activations
__device__ float g_ctx [(size_t)MR * DM];   // 16 MB attention output
__device__ __nv_bfloat16 g_xhi [(size_t)MR * DM];
__device__ __nv_bfloat16 g_xlo [(size_t)MR * DM];
__device__ __nv_bfloat16 g_whiT[(size_t)N3 * DM];   // W_qkv^T (n-major, K contiguous)
__device__ __nv_bfloat16 g_wloT[(size_t)N3 * DM];
__device__ __nv_bfloat16 g_phiT[(size_t)DM * DM];   // c_proj^T
__device__ __nv_bfloat16 g_ploT[(size_t)DM * DM];
__device__ __nv_bfloat16 g_chi [(size_t)MR * DM];
__device__ __nv_bfloat16 g_clo [(size_t)MR * DM];

// ============================ helpers ============================
__device__ __forceinline__ uint32_t smem_u32(const void* p) {
    uint32_t a;
    asm("{ .reg .u64 t; cvta.to.shared.u64 t, %1; cvt.u32.u64 %0, t; }" : "=r"(a) : "l"(p));
    return a;
}
__device__ __forceinline__ void cp16(uint32_t s, const void* g) {
    asm volatile("cp.async.cg.shared.global [%0], [%1], 16;" :: "r"(s), "l"(g));
}
#define CP_COMMIT() asm volatile("cp.async.commit_group;" ::: "memory")

__device__ __forceinline__ void ldm4(uint32_t& r0, uint32_t& r1, uint32_t& r2, uint32_t& r3,
                                     uint32_t addr) {
    asm volatile("ldmatrix.sync.aligned.m8n8.x4.shared.b16 {%0,%1,%2,%3}, [%4];"
                 : "=r"(r0), "=r"(r1), "=r"(r2), "=r"(r3) : "r"(addr));
}
__device__ __forceinline__ void mma_bf16(float* d, const uint32_t* a, uint32_t b0, uint32_t b1) {
    asm volatile("mma.sync.aligned.m16n8k16.row.col.f32.bf16.bf16.f32 "
                 "{%0,%1,%2,%3}, {%4,%5,%6,%7}, {%8,%9}, {%0,%1,%2,%3};"
                 : "+f"(d[0]), "+f"(d[1]), "+f"(d[2]), "+f"(d[3])
                 : "r"(a[0]), "r"(a[1]), "r"(a[2]), "r"(a[3]), "r"(b0), "r"(b1));
}

// ================== prep: split fp32 -> bf16 hi/lo ==================
__global__ void split_kernel(const float* __restrict__ in,
                             __nv_bfloat16* __restrict__ hi,
                             __nv_bfloat16* __restrict__ lo, int n)
{
    int i = blockIdx.x * 256 + threadIdx.x;
    if (i >= n) return;
    float v = in[i];
    __nv_bfloat16 h = __float2bfloat16(v);
    hi[i] = h;
    lo[i] = __float2bfloat16(v - __bfloat162float(h));
}

// ====== prep: fold LoRA, split to bf16 hi/lo, transpose (K-contig rows) ======
__global__ __launch_bounds__(256) void fold_split_T_kernel(
    const float* __restrict__ W, const float* __restrict__ A, const float* __restrict__ Bm,
    __nv_bfloat16* __restrict__ hiT, __nv_bfloat16* __restrict__ loT, int N, int K)
{
    __shared__ float sv[32][33];
    const int k0 = blockIdx.y * 32, n0 = blockIdx.x * 32;
    const int r = threadIdx.x >> 5, c = threadIdx.x & 31;
#pragma unroll
    for (int i = 0; i < 4; ++i) {
        int k = k0 + i * 8 + r, n = n0 + c;
        float s = 0.f;
#pragma unroll
        for (int rr = 0; rr < RANK; ++rr)
            s = fmaf(A[k * RANK + rr], Bm[rr * N + n], s);
        sv[i * 8 + r][c] = W[(size_t)k * N + n] + 2.0f * s;
    }
    __syncthreads();
#pragma unroll
    for (int i = 0; i < 4; ++i) {
        int n = n0 + i * 8 + r, k = k0 + c;
        float v = sv[c][i * 8 + r];
        __nv_bfloat16 h = __float2bfloat16(v);
        hiT[(size_t)n * K + k] = h;
        loT[(size_t)n * K + k] = __float2bfloat16(v - __bfloat162float(h));
    }
}

// ================== mma.sync GEMM: C = A(MxK) @ B^T + bias ==================
// A row-major [M x K] bf16 (hi+lo); B stored transposed [N x K] bf16 (hi+lo).
// CTA tile 128x128, BK=32, 8 warps (2x4), warp tile 64x32. bf16x3 compensated.
#define BK 32
#define AST 40                       // smem row stride in bf16 (80 bytes)
#define TILE_ELT (128 * AST)         // bf16 per tile (5120) = 10240 B
#define STAGE_ELT (4 * TILE_ELT)     // Ah, Al, Bh, Bl
#define GSMEM (2 * STAGE_ELT * 2)    // 2 stages, bytes = 81920

__global__ __launch_bounds__(256) void mma_gemm_kernel(
    const __nv_bfloat16* __restrict__ Ahi, const __nv_bfloat16* __restrict__ Alo,
    const __nv_bfloat16* __restrict__ Bhi, const __nv_bfloat16* __restrict__ Blo,
    const float* __restrict__ bias, float* __restrict__ C, int K, int N)
{
    extern __shared__ __nv_bfloat16 dsm[];
    const uint32_t sbase = smem_u32(dsm);

    const int tid = threadIdx.x, wid = tid >> 5, lane = tid & 31;
    const int row0 = blockIdx.y * 128, col0 = blockIdx.x * 128;
    const int wm = (wid & 1) * 64, wn = (wid >> 1) * 32;

    const __nv_bfloat16* gsrc[4] = { Ahi, Alo, Bhi, Blo };

    float acc[4][4][4] = {};

    // per-lane ldmatrix offsets (bytes within a tile)
    const int a_row_l = wm + (lane & 15);
    const int a_k_l   = (lane >> 4) * 8;
    const int b_n_l   = wn + ((lane >> 3) & 1) * 8 + (lane & 7);
    const int b_k_l   = (lane >> 4) * 8;

    const int iters = K / BK;

    // ---- stage loader: 8 chunks of 16B per thread ----
    auto load_stage = [&](int s, int k0) {
        const uint32_t sb = sbase + s * STAGE_ELT * 2;
#pragma unroll
        for (int t = 0; t < 8; ++t) {
            int idx = tid + t * 256;          // 0..2047
            int a = idx >> 9, c = idx & 511;  // array, chunk
            int r = c >> 2, kk = (c & 3) * 8; // tile row, k offset (bf16)
            int grow = (a < 2 ? row0 : col0) + r;
            const __nv_bfloat16* g = gsrc[a] + (size_t)grow * K + k0 + kk;
            cp16(sb + (a * TILE_ELT + r * AST + kk) * 2, g);
        }
    };

    load_stage(0, 0);
    CP_COMMIT();

    for (int it = 0; it < iters; ++it) {
        if (it + 1 < iters) {
            load_stage((it + 1) & 1, (it + 1) * BK);
            CP_COMMIT();
            asm volatile("cp.async.wait_group 1;" ::: "memory");
        } else {
            asm volatile("cp.async.wait_group 0;" ::: "memory");
        }
        __syncthreads();

        const uint32_t sb  = sbase + (it & 1) * STAGE_ELT * 2;
        const uint32_t bAh = sb;
        const uint32_t bAl = sb + TILE_ELT * 2;
        const uint32_t bBh = sb + 2 * TILE_ELT * 2;
        const uint32_t bBl = sb + 3 * TILE_ELT * 2;

#pragma unroll
        for (int ks = 0; ks < 2; ++ks) {
            // B fragments: 2 n-pairs x {b0(t0),b0(t1),b1(t0),b1(t1)}
            uint32_t bh[2][4], bl[2][4];
#pragma unroll
            for (int np = 0; np < 2; ++np) {
                uint32_t off = (uint32_t)((b_n_l + np * 16) * AST + ks * 16 + b_k_l) * 2;
                ldm4(bh[np][0], bh[np][1], bh[np][2], bh[np][3], bBh + off);
                ldm4(bl[np][0], bl[np][1], bl[np][2], bl[np][3], bBl + off);
            }
#pragma unroll
            for (int mt = 0; mt < 4; ++mt) {
                uint32_t aoff = (uint32_t)((a_row_l + mt * 16) * AST + ks * 16 + a_k_l) * 2;
                uint32_t ah[4], al[4];
                ldm4(ah[0], ah[1], ah[2], ah[3], bAh + aoff);
                ldm4(al[0], al[1], al[2], al[3], bAl + aoff);
#pragma unroll
                for (int nt = 0; nt < 4; ++nt) {
                    const int np = nt >> 1, hh = nt & 1;
                    mma_bf16(acc[mt][nt], ah, bh[np][hh], bh[np][2 + hh]);
                    mma_bf16(acc[mt][nt], ah, bl[np][hh], bl[np][2 + hh]);
                    mma_bf16(acc[mt][nt], al, bh[np][hh], bh[np][2 + hh]);
                }
            }
        }
        __syncthreads();
    }

    // ---- epilogue: direct fp32 stores + bias ----
#pragma unroll
    for (int mt = 0; mt < 4; ++mt) {
#pragma unroll
        for (int nt = 0; nt < 4; ++nt) {
            int rr = row0 + wm + mt * 16 + (lane >> 2);
            int cc = col0 + wn + nt * 8 + (lane & 3) * 2;
            float bx = bias[cc], by = bias[cc + 1];
            float2 v0 = { acc[mt][nt][0] + bx, acc[mt][nt][1] + by };
            float2 v1 = { acc[mt][nt][2] + bx, acc[mt][nt][3] + by };
            *(float2*)&C[(size_t)rr * N + cc]       = v0;
            *(float2*)&C[(size_t)(rr + 8) * N + cc] = v1;
        }
    }
}

// ---------------- flash attention: BM=BN=64, Dh=64, fp32 online softmax ----------------
#define FST 65
#define FLASH_SMEM ((4*64*FST + 3*64) * 4 + 64 * 4)

__global__ __launch_bounds__(256) void flash_kernel(const int* __restrict__ amask)
{
    extern __shared__ float sm[];
    float* q_s = sm;
    float* k_s = q_s + 64 * FST;
    float* v_s = k_s + 64 * FST;
    float* p_s = v_s + 64 * FST;
    float* m_s = p_s + 64 * FST;
    float* l_s = m_s + 64;
    float* a_s = l_s + 64;
    int*   msk = (int*)(a_s + 64);

    const int qt = blockIdx.x, h = blockIdx.y, b = blockIdx.z;
    const int tid = threadIdx.x;
    const int tx = tid & 15, ty = tid >> 4;
    const int wid = tid >> 5, lane = tid & 31;
    const int q0 = qt * 64;

    for (int i = tid; i < 64 * 16; i += 256) {
        int r = i >> 4, c4 = (i & 15) << 2;
        float4 v = *(const float4*)&g_qkv[(size_t)(b * SQ + q0 + r) * N3 + h * DH + c4];
        q_s[r * FST + c4 + 0] = v.x; q_s[r * FST + c4 + 1] = v.y;
        q_s[r * FST + c4 + 2] = v.z; q_s[r * FST + c4 + 3] = v.w;
    }
    if (tid < 64) { m_s[tid] = -1e30f; l_s[tid] = 0.f; }

    float o[4][4] = {};

    for (int kt = 0; kt <= qt; ++kt) {
        __syncthreads();
        const int kb = kt * 64;
        for (int i = tid; i < 64 * 16; i += 256) {
            int r = i >> 4, c4 = (i & 15) << 2;
            size_t g = (size_t)(b * SQ + kb + r) * N3 + DM + h * DH + c4;
            float4 kv = *(const float4*)&g_qkv[g];
            float4 vv = *(const float4*)&g_qkv[g + DM];
            k_s[r * FST + c4 + 0] = kv.x; k_s[r * FST + c4 + 1] = kv.y;
            k_s[r * FST + c4 + 2] = kv.z; k_s[r * FST + c4 + 3] = kv.w;
            v_s[r * FST + c4 + 0] = vv.x; v_s[r * FST + c4 + 1] = vv.y;
            v_s[r * FST + c4 + 2] = vv.z; v_s[r * FST + c4 + 3] = vv.w;
        }
        if (tid < 64) msk[tid] = amask[b * SQ + kb + tid];
        __syncthreads();

        float sa[4][4] = {};
#pragma unroll 4
        for (int d = 0; d < 64; ++d) {
            float qa[4], kv[4];
#pragma unroll
            for (int i = 0; i < 4; ++i) qa[i] = q_s[(ty * 4 + i) * FST + d];
#pragma unroll
            for (int j = 0; j < 4; ++j) kv[j] = k_s[(tx * 4 + j) * FST + d];
#pragma unroll
            for (int i = 0; i < 4; ++i)
#pragma unroll
                for (int j = 0; j < 4; ++j)
                    sa[i][j] = fmaf(qa[i], kv[j], sa[i][j]);
        }
#pragma unroll
        for (int i = 0; i < 4; ++i) {
            const int rg = q0 + ty * 4 + i;
#pragma unroll
            for (int j = 0; j < 4; ++j) {
                const int cj = tx * 4 + j;
                const int cg = kb + cj;
                float sv = (cg > rg || msk[cj] == 0) ? NEGBIG : sa[i][j] * 0.125f;
                p_s[(ty * 4 + i) * FST + cj] = sv;
            }
        }
        __syncthreads();

#pragma unroll
        for (int rr = 0; rr < 8; ++rr) {
            const int r = wid * 8 + rr;
            float s0 = p_s[r * FST + lane];
            float s1 = p_s[r * FST + 32 + lane];
            float mx = fmaxf(s0, s1);
#pragma unroll
            for (int off = 16; off; off >>= 1)
                mx = fmaxf(mx, __shfl_xor_sync(0xffffffffu, mx, off));
            float mold = m_s[r];
            float mnew = fmaxf(mold, mx);
            float p0 = __expf(s0 - mnew);
            float p1 = __expf(s1 - mnew);
            p_s[r * FST + lane]      = p0;
            p_s[r * FST + 32 + lane] = p1;
            float sum = p0 + p1;
#pragma unroll
            for (int off = 16; off; off >>= 1)
                sum += __shfl_xor_sync(0xffffffffu, sum, off);
            if (lane == 0) {
                float al = __expf(mold - mnew);
                a_s[r] = al;
                l_s[r] = l_s[r] * al + sum;
                m_s[r] = mnew;
            }
        }
        __syncthreads();

        float al[4];
#pragma unroll
        for (int i = 0; i < 4; ++i) al[i] = a_s[ty * 4 + i];
#pragma unroll
        for (int i = 0; i < 4; ++i)
#pragma unroll
            for (int j = 0; j < 4; ++j) o[i][j] *= al[i];

#pragma unroll 4
        for (int kk = 0; kk < 64; ++kk) {
            float pv[4], vv[4];
#pragma unroll
            for (int i = 0; i < 4; ++i) pv[i] = p_s[(ty * 4 + i) * FST + kk];
#pragma unroll
            for (int j = 0; j < 4; ++j) vv[j] = v_s[kk * FST + tx * 4 + j];
#pragma unroll
            for (int i = 0; i < 4; ++i)
#pragma unroll
                for (int j = 0; j < 4; ++j)
                    o[i][j] = fmaf(pv[i], vv[j], o[i][j]);
        }
    }

#pragma unroll
    for (int i = 0; i < 4; ++i) {
        const int rg = q0 + ty * 4 + i;
        const float inv = 1.0f / l_s[ty * 4 + i];
#pragma unroll
        for (int j = 0; j < 4; ++j)
            g_ctx[(size_t)(b * SQ + rg) * DM + h * DH + tx * 4 + j] = o[i][j] * inv;
    }
}

// ---------------- launch ----------------
extern "C" void kernel_launch(void* const* d_in, const int* in_sizes, int n_in,
                              void* d_out, int out_size)
{
    const float* x     = (const float*)d_in[0];
    const int*   amask = (const int*)  d_in[1];
    const float* Wqkv  = (const float*)d_in[2];
    const float* bqkv  = (const float*)d_in[3];
    const float* Aqkv  = (const float*)d_in[4];
    const float* Bqkv  = (const float*)d_in[5];
    const float* Wproj = (const float*)d_in[6];
    const float* bproj = (const float*)d_in[7];
    const float* Aproj = (const float*)d_in[8];
    const float* Bproj = (const float*)d_in[9];
    float* out = (float*)d_out;

    float *qkv, *ctx;
    __nv_bfloat16 *xhi, *xlo, *whiT, *wloT, *phiT, *ploT, *chi, *clo;
    cudaGetSymbolAddress((void**)&qkv,  g_qkv);
    cudaGetSymbolAddress((void**)&ctx,  g_ctx);
    cudaGetSymbolAddress((void**)&xhi,  g_xhi);
    cudaGetSymbolAddress((void**)&xlo,  g_xlo);
    cudaGetSymbolAddress((void**)&whiT, g_whiT);
    cudaGetSymbolAddress((void**)&wloT, g_wloT);
    cudaGetSymbolAddress((void**)&phiT, g_phiT);
    cudaGetSymbolAddress((void**)&ploT, g_ploT);
    cudaGetSymbolAddress((void**)&chi,  g_chi);
    cudaGetSymbolAddress((void**)&clo,  g_clo);

    cudaFuncSetAttribute(mma_gemm_kernel, cudaFuncAttributeMaxDynamicSharedMemorySize, GSMEM);
    cudaFuncSetAttribute(flash_kernel,    cudaFuncAttributeMaxDynamicSharedMemorySize, FLASH_SMEM);

    // prep: split x, fold+split+transpose weights
    split_kernel<<<(MR * DM + 255) / 256, 256>>>(x, xhi, xlo, MR * DM);
    fold_split_T_kernel<<<dim3(N3 / 32, DM / 32), 256>>>(Wqkv,  Aqkv,  Bqkv,  whiT, wloT, N3, DM);
    fold_split_T_kernel<<<dim3(DM / 32, DM / 32), 256>>>(Wproj, Aproj, Bproj, phiT, ploT, DM, DM);

    // qkv = x @ W_eff + bias   (mma.sync bf16x3)
    mma_gemm_kernel<<<dim3(N3 / 128, MR / 128), 256, GSMEM>>>(xhi, xlo, whiT, wloT, bqkv, qkv, DM, N3);

    // flash attention -> ctx
    flash_kernel<<<dim3(SQ / 64, NH, BB), 256, FLASH_SMEM>>>(amask);

    // out = ctx @ C_eff + bias (mma.sync bf16x3)
    split_kernel<<<(MR * DM + 255) / 256, 256>>>(ctx, chi, clo, MR * DM);
    mma_gemm_kernel<<<dim3(DM / 128, MR / 128), 256, GSMEM>>>(chi, clo, phiT, ploT, bproj, out, DM, DM);
}

// round 5
// speedup vs baseline: 2.7085x; 2.0020x over previous
#include <cuda_runtime.h>
#include <cuda_bf16.h>
#include <cstdint>

#define DM   1024
#define NH   16
#define DH   64
#define SQ   2048
#define BB   2
#define MR   (BB*SQ)      // 4096 token rows
#define N3   (3*DM)       // 3072
#define RANK 8
#define NEGBIG (-1.25e8f) // -1e9 / sqrt(64)

// ---------------- scratch (static __device__, no allocations) ----------------
__device__ __nv_bfloat16 g_qkvh[(size_t)MR * N3];   // qkv hi (24 MB)
__device__ __nv_bfloat16 g_qkvl[(size_t)MR * N3];   // qkv lo
__device__ __nv_bfloat16 g_xhi [(size_t)MR * DM];
__device__ __nv_bfloat16 g_xlo [(size_t)MR * DM];
__device__ __nv_bfloat16 g_whiT[(size_t)N3 * DM];   // W_qkv^T (K contiguous)
__device__ __nv_bfloat16 g_wloT[(size_t)N3 * DM];
__device__ __nv_bfloat16 g_phiT[(size_t)DM * DM];   // c_proj^T
__device__ __nv_bfloat16 g_ploT[(size_t)DM * DM];
__device__ __nv_bfloat16 g_chi [(size_t)MR * DM];   // ctx hi
__device__ __nv_bfloat16 g_clo [(size_t)MR * DM];   // ctx lo

// ============================ helpers ============================
__device__ __forceinline__ uint32_t smem_u32(const void* p) {
    uint32_t a;
    asm("{ .reg .u64 t; cvta.to.shared.u64 t, %1; cvt.u32.u64 %0, t; }" : "=r"(a) : "l"(p));
    return a;
}
__device__ __forceinline__ void cp16(uint32_t s, const void* g) {
    asm volatile("cp.async.cg.shared.global [%0], [%1], 16;" :: "r"(s), "l"(g));
}
#define CP_COMMIT() asm volatile("cp.async.commit_group;" ::: "memory")

__device__ __forceinline__ void ldm4(uint32_t& r0, uint32_t& r1, uint32_t& r2, uint32_t& r3,
                                     uint32_t addr) {
    asm volatile("ldmatrix.sync.aligned.m8n8.x4.shared.b16 {%0,%1,%2,%3}, [%4];"
                 : "=r"(r0), "=r"(r1), "=r"(r2), "=r"(r3) : "r"(addr));
}
__device__ __forceinline__ void ldm4t(uint32_t& r0, uint32_t& r1, uint32_t& r2, uint32_t& r3,
                                      uint32_t addr) {
    asm volatile("ldmatrix.sync.aligned.m8n8.x4.trans.shared.b16 {%0,%1,%2,%3}, [%4];"
                 : "=r"(r0), "=r"(r1), "=r"(r2), "=r"(r3) : "r"(addr));
}
__device__ __forceinline__ void mma_bf16(float* d, const uint32_t* a, uint32_t b0, uint32_t b1) {
    asm volatile("mma.sync.aligned.m16n8k16.row.col.f32.bf16.bf16.f32 "
                 "{%0,%1,%2,%3}, {%4,%5,%6,%7}, {%8,%9}, {%0,%1,%2,%3};"
                 : "+f"(d[0]), "+f"(d[1]), "+f"(d[2]), "+f"(d[3])
                 : "r"(a[0]), "r"(a[1]), "r"(a[2]), "r"(a[3]), "r"(b0), "r"(b1));
}
__device__ __forceinline__ void split2(float x, float y, uint32_t& hi, uint32_t& lo) {
    __nv_bfloat16 hx = __float2bfloat16(x), hy = __float2bfloat16(y);
    __nv_bfloat162 h2; h2.x = hx; h2.y = hy;
    __nv_bfloat162 l2;
    l2.x = __float2bfloat16(x - __bfloat162float(hx));
    l2.y = __float2bfloat16(y - __bfloat162float(hy));
    hi = *(uint32_t*)&h2; lo = *(uint32_t*)&l2;
}

// ================== prep: split fp32 -> bf16 hi/lo ==================
__global__ void split_kernel(const float* __restrict__ in,
                             __nv_bfloat16* __restrict__ hi,
                             __nv_bfloat16* __restrict__ lo, int n)
{
    int i = blockIdx.x * 256 + threadIdx.x;
    if (i >= n) return;
    float v = in[i];
    __nv_bfloat16 h = __float2bfloat16(v);
    hi[i] = h;
    lo[i] = __float2bfloat16(v - __bfloat162float(h));
}

// ====== prep: fold LoRA, split to bf16 hi/lo, transpose (K-contig rows) ======
__global__ __launch_bounds__(256) void fold_split_T_kernel(
    const float* __restrict__ W, const float* __restrict__ A, const float* __restrict__ Bm,
    __nv_bfloat16* __restrict__ hiT, __nv_bfloat16* __restrict__ loT, int N, int K)
{
    __shared__ float sv[32][33];
    const int k0 = blockIdx.y * 32, n0 = blockIdx.x * 32;
    const int r = threadIdx.x >> 5, c = threadIdx.x & 31;
#pragma unroll
    for (int i = 0; i < 4; ++i) {
        int k = k0 + i * 8 + r, n = n0 + c;
        float s = 0.f;
#pragma unroll
        for (int rr = 0; rr < RANK; ++rr)
            s = fmaf(A[k * RANK + rr], Bm[rr * N + n], s);
        sv[i * 8 + r][c] = W[(size_t)k * N + n] + 2.0f * s;
    }
    __syncthreads();
#pragma unroll
    for (int i = 0; i < 4; ++i) {
        int n = n0 + i * 8 + r, k = k0 + c;
        float v = sv[c][i * 8 + r];
        __nv_bfloat16 h = __float2bfloat16(v);
        hiT[(size_t)n * K + k] = h;
        loT[(size_t)n * K + k] = __float2bfloat16(v - __bfloat162float(h));
    }
}

// ================== mma.sync GEMM: C = A(MxK) @ B^T + bias ==================
#define BK 32
#define AST 40
#define TILE_ELT (128 * AST)
#define STAGE_ELT (4 * TILE_ELT)
#define GSMEM (2 * STAGE_ELT * 2)

__global__ __launch_bounds__(256) void mma_gemm_kernel(
    const __nv_bfloat16* __restrict__ Ahi, const __nv_bfloat16* __restrict__ Alo,
    const __nv_bfloat16* __restrict__ Bhi, const __nv_bfloat16* __restrict__ Blo,
    const float* __restrict__ bias, float* __restrict__ C,
    __nv_bfloat16* __restrict__ Chi, __nv_bfloat16* __restrict__ Clo,
    int K, int N, int mode)
{
    extern __shared__ __nv_bfloat16 dsm[];
    const uint32_t sbase = smem_u32(dsm);

    const int tid = threadIdx.x, wid = tid >> 5, lane = tid & 31;
    const int row0 = blockIdx.y * 128, col0 = blockIdx.x * 128;
    const int wm = (wid & 1) * 64, wn = (wid >> 1) * 32;

    const __nv_bfloat16* gsrc[4] = { Ahi, Alo, Bhi, Blo };

    float acc[4][4][4] = {};

    const int a_row_l = wm + (lane & 15);
    const int a_k_l   = (lane >> 4) * 8;
    const int b_n_l   = wn + ((lane >> 3) & 1) * 8 + (lane & 7);
    const int b_k_l   = (lane >> 4) * 8;

    const int iters = K / BK;

    auto load_stage = [&](int s, int k0) {
        const uint32_t sb = sbase + s * STAGE_ELT * 2;
#pragma unroll
        for (int t = 0; t < 8; ++t) {
            int idx = tid + t * 256;
            int a = idx >> 9, c = idx & 511;
            int r = c >> 2, kk = (c & 3) * 8;
            int grow = (a < 2 ? row0 : col0) + r;
            const __nv_bfloat16* g = gsrc[a] + (size_t)grow * K + k0 + kk;
            cp16(sb + (a * TILE_ELT + r * AST + kk) * 2, g);
        }
    };

    load_stage(0, 0);
    CP_COMMIT();

    for (int it = 0; it < iters; ++it) {
        if (it + 1 < iters) {
            load_stage((it + 1) & 1, (it + 1) * BK);
            CP_COMMIT();
            asm volatile("cp.async.wait_group 1;" ::: "memory");
        } else {
            asm volatile("cp.async.wait_group 0;" ::: "memory");
        }
        __syncthreads();

        const uint32_t sb  = sbase + (it & 1) * STAGE_ELT * 2;
        const uint32_t bAh = sb;
        const uint32_t bAl = sb + TILE_ELT * 2;
        const uint32_t bBh = sb + 2 * TILE_ELT * 2;
        const uint32_t bBl = sb + 3 * TILE_ELT * 2;

#pragma unroll
        for (int ks = 0; ks < 2; ++ks) {
            uint32_t bh[2][4], bl[2][4];
#pragma unroll
            for (int np = 0; np < 2; ++np) {
                uint32_t off = (uint32_t)((b_n_l + np * 16) * AST + ks * 16 + b_k_l) * 2;
                ldm4(bh[np][0], bh[np][1], bh[np][2], bh[np][3], bBh + off);
                ldm4(bl[np][0], bl[np][1], bl[np][2], bl[np][3], bBl + off);
            }
#pragma unroll
            for (int mt = 0; mt < 4; ++mt) {
                uint32_t aoff = (uint32_t)((a_row_l + mt * 16) * AST + ks * 16 + a_k_l) * 2;
                uint32_t ah[4], al[4];
                ldm4(ah[0], ah[1], ah[2], ah[3], bAh + aoff);
                ldm4(al[0], al[1], al[2], al[3], bAl + aoff);
#pragma unroll
                for (int nt = 0; nt < 4; ++nt) {
                    const int np = nt >> 1, hh = nt & 1;
                    mma_bf16(acc[mt][nt], ah, bh[np][hh], bh[np][2 + hh]);
                    mma_bf16(acc[mt][nt], ah, bl[np][hh], bl[np][2 + hh]);
                    mma_bf16(acc[mt][nt], al, bh[np][hh], bh[np][2 + hh]);
                }
            }
        }
        __syncthreads();
    }

#pragma unroll
    for (int mt = 0; mt < 4; ++mt) {
#pragma unroll
        for (int nt = 0; nt < 4; ++nt) {
            int rr = row0 + wm + mt * 16 + (lane >> 2);
            int cc = col0 + wn + nt * 8 + (lane & 3) * 2;
            float bx = bias[cc], by = bias[cc + 1];
            float v0 = acc[mt][nt][0] + bx, v1 = acc[mt][nt][1] + by;
            float v2 = acc[mt][nt][2] + bx, v3 = acc[mt][nt][3] + by;
            if (mode == 0) {
                *(float2*)&C[(size_t)rr * N + cc]       = make_float2(v0, v1);
                *(float2*)&C[(size_t)(rr + 8) * N + cc] = make_float2(v2, v3);
            } else {
                uint32_t hi, lo;
                split2(v0, v1, hi, lo);
                *(uint32_t*)&Chi[(size_t)rr * N + cc] = hi;
                *(uint32_t*)&Clo[(size_t)rr * N + cc] = lo;
                split2(v2, v3, hi, lo);
                *(uint32_t*)&Chi[(size_t)(rr + 8) * N + cc] = hi;
                *(uint32_t*)&Clo[(size_t)(rr + 8) * N + cc] = lo;
            }
        }
    }
}

// ============== flash attention, mma.sync bf16x3, BM=128 BN=64 ==============
#define FKST 72
#define Q_BYTES (128*FKST*2)                 // 18432
#define KV_BYTES (64*FKST*2)                 // 9216
#define STG_BYTES (4*KV_BYTES)               // 36864
#define MSK_OFF (2*Q_BYTES + 2*STG_BYTES)    // 110592
#define FL_SMEM (MSK_OFF + 512)

__global__ __launch_bounds__(256) void flash_mma_kernel(const int* __restrict__ amask)
{
    extern __shared__ char fsm[];
    const uint32_t sb = smem_u32(fsm);
    int* mskp = (int*)(fsm + MSK_OFF);

    const int qt = (gridDim.x - 1) - blockIdx.x;   // heavy tiles first
    const int h = blockIdx.y, b = blockIdx.z;
    const int tid = threadIdx.x, wid = tid >> 5, lane = tid & 31;
    const int q0 = qt * 128, wrow = wid * 16;

    auto load_q = [&]() {
#pragma unroll
        for (int t = 0; t < 8; ++t) {
            int idx = tid + t * 256;
            int a = idx >> 10, c = idx & 1023, r = c >> 3, ch = c & 7;
            const __nv_bfloat16* g = (a ? g_qkvl : g_qkvh)
                + (size_t)(b * SQ + q0 + r) * N3 + h * DH + ch * 8;
            cp16(sb + a * Q_BYTES + r * 144 + ch * 16, g);
        }
    };
    auto load_kv = [&](int s, int kb) {
        const uint32_t base = sb + 2 * Q_BYTES + s * STG_BYTES;
#pragma unroll
        for (int t = 0; t < 8; ++t) {
            int idx = tid + t * 256;
            int a = idx >> 9, c = idx & 511, r = c >> 3, ch = c & 7;
            const __nv_bfloat16* g = ((a & 1) ? g_qkvl : g_qkvh)
                + (size_t)(b * SQ + kb + r) * N3 + ((a >> 1) ? 2 * DM : DM) + h * DH + ch * 8;
            cp16(base + a * KV_BYTES + r * 144 + ch * 16, g);
        }
        if (tid < 64) mskp[s * 64 + tid] = amask[b * SQ + kb + tid];
    };

    load_q();
    load_kv(0, 0);
    CP_COMMIT();

    const int ktmax = 2 * qt + 1;
    float m0 = -1e30f, m1 = -1e30f, l0 = 0.f, l1 = 0.f;
    float oacc[8][4] = {};
    uint32_t qh[4][4], ql[4][4];

    const int arow = wrow + (lane & 15), ak2 = (lane >> 4) * 16;
    const int brow = ((lane >> 3) & 1) * 8 + (lane & 7), bk2 = (lane >> 4) * 16;
    const int vrow = ((lane >> 3) & 1) * 8 + (lane & 7);
    const int vcol = ((lane >> 4) & 1) * 16;
    const int g0 = q0 + wrow + (lane >> 2), g1 = g0 + 8;

    for (int kt = 0; kt <= ktmax; ++kt) {
        if (kt < ktmax) {
            load_kv((kt + 1) & 1, (kt + 1) * 64);
            CP_COMMIT();
            asm volatile("cp.async.wait_group 1;" ::: "memory");
        } else {
            asm volatile("cp.async.wait_group 0;" ::: "memory");
        }
        __syncthreads();

        if (kt == 0) {
#pragma unroll
            for (int ks = 0; ks < 4; ++ks) {
                uint32_t off = (uint32_t)(arow * 144 + ks * 32 + ak2);
                ldm4(qh[ks][0], qh[ks][1], qh[ks][2], qh[ks][3], sb + off);
                ldm4(ql[ks][0], ql[ks][1], ql[ks][2], ql[ks][3], sb + Q_BYTES + off);
            }
        }

        const uint32_t kh_b = sb + 2 * Q_BYTES + (kt & 1) * STG_BYTES;
        const uint32_t kl_b = kh_b + KV_BYTES;
        const uint32_t vh_b = kh_b + 2 * KV_BYTES;
        const uint32_t vl_b = kh_b + 3 * KV_BYTES;
        const int* msk = mskp + (kt & 1) * 64;
        const int kb = kt * 64;

        // ---- S = Q K^T (bf16x3) ----
        float sc[8][4] = {};
#pragma unroll
        for (int ks = 0; ks < 4; ++ks) {
#pragma unroll
            for (int np = 0; np < 4; ++np) {
                uint32_t kh4[4], kl4[4];
                uint32_t off = (uint32_t)((np * 16 + brow) * 144 + ks * 32 + bk2);
                ldm4(kh4[0], kh4[1], kh4[2], kh4[3], kh_b + off);
                ldm4(kl4[0], kl4[1], kl4[2], kl4[3], kl_b + off);
#pragma unroll
                for (int hh = 0; hh < 2; ++hh) {
                    float* d = sc[np * 2 + hh];
                    mma_bf16(d, qh[ks], kh4[hh], kh4[2 + hh]);
                    mma_bf16(d, qh[ks], kl4[hh], kl4[2 + hh]);
                    mma_bf16(d, ql[ks], kh4[hh], kh4[2 + hh]);
                }
            }
        }

        // ---- mask (causal + pad) then scale ----
#pragma unroll
        for (int nt = 0; nt < 8; ++nt) {
            int cb = (nt >> 1) * 16 + (nt & 1) * 8 + (lane & 3) * 2;
            int c0 = kb + cb;
            bool p0 = msk[cb] != 0, p1 = msk[cb + 1] != 0;
            sc[nt][0] = (!p0 || c0 > g0)     ? NEGBIG : sc[nt][0] * 0.125f;
            sc[nt][1] = (!p1 || c0 + 1 > g0) ? NEGBIG : sc[nt][1] * 0.125f;
            sc[nt][2] = (!p0 || c0 > g1)     ? NEGBIG : sc[nt][2] * 0.125f;
            sc[nt][3] = (!p1 || c0 + 1 > g1) ? NEGBIG : sc[nt][3] * 0.125f;
        }

        // ---- online softmax (rows g0, g1) ----
        float mx0 = -1e30f, mx1 = -1e30f;
#pragma unroll
        for (int nt = 0; nt < 8; ++nt) {
            mx0 = fmaxf(mx0, fmaxf(sc[nt][0], sc[nt][1]));
            mx1 = fmaxf(mx1, fmaxf(sc[nt][2], sc[nt][3]));
        }
        mx0 = fmaxf(mx0, __shfl_xor_sync(0xffffffffu, mx0, 1));
        mx0 = fmaxf(mx0, __shfl_xor_sync(0xffffffffu, mx0, 2));
        mx1 = fmaxf(mx1, __shfl_xor_sync(0xffffffffu, mx1, 1));
        mx1 = fmaxf(mx1, __shfl_xor_sync(0xffffffffu, mx1, 2));
        float mn0 = fmaxf(m0, mx0), mn1 = fmaxf(m1, mx1);
        float al0 = __expf(m0 - mn0), al1 = __expf(m1 - mn1);
        m0 = mn0; m1 = mn1;
        float sum0 = 0.f, sum1 = 0.f;
#pragma unroll
        for (int nt = 0; nt < 8; ++nt) {
            sc[nt][0] = __expf(sc[nt][0] - mn0);
            sc[nt][1] = __expf(sc[nt][1] - mn0);
            sc[nt][2] = __expf(sc[nt][2] - mn1);
            sc[nt][3] = __expf(sc[nt][3] - mn1);
            sum0 += sc[nt][0] + sc[nt][1];
            sum1 += sc[nt][2] + sc[nt][3];
        }
        sum0 += __shfl_xor_sync(0xffffffffu, sum0, 1);
        sum0 += __shfl_xor_sync(0xffffffffu, sum0, 2);
        sum1 += __shfl_xor_sync(0xffffffffu, sum1, 1);
        sum1 += __shfl_xor_sync(0xffffffffu, sum1, 2);
        l0 = l0 * al0 + sum0;
        l1 = l1 * al1 + sum1;
#pragma unroll
        for (int nt = 0; nt < 8; ++nt) {
            oacc[nt][0] *= al0; oacc[nt][1] *= al0;
            oacc[nt][2] *= al1; oacc[nt][3] *= al1;
        }

        // ---- O += P V (bf16x3, P split in registers) ----
        // V trans-ldm register order: r0=(k0,d0) r1=(k8,d0) r2=(k0,d8) r3=(k8,d8)
        // => d-half dh pairs (r[2*dh], r[2*dh+1])  [THE R4 BUG was (r[dh], r[2+dh])]
#pragma unroll
        for (int ks2 = 0; ks2 < 4; ++ks2) {
            uint32_t ah[4], alr[4];
            split2(sc[2 * ks2][0],     sc[2 * ks2][1],     ah[0], alr[0]);
            split2(sc[2 * ks2][2],     sc[2 * ks2][3],     ah[1], alr[1]);
            split2(sc[2 * ks2 + 1][0], sc[2 * ks2 + 1][1], ah[2], alr[2]);
            split2(sc[2 * ks2 + 1][2], sc[2 * ks2 + 1][3], ah[3], alr[3]);
#pragma unroll
            for (int dn = 0; dn < 4; ++dn) {
                uint32_t vh4[4], vl4[4];
                uint32_t voff = (uint32_t)((ks2 * 16 + vrow) * 144 + dn * 32 + vcol);
                ldm4t(vh4[0], vh4[1], vh4[2], vh4[3], vh_b + voff);
                ldm4t(vl4[0], vl4[1], vl4[2], vl4[3], vl_b + voff);
#pragma unroll
                for (int dh = 0; dh < 2; ++dh) {
                    float* o = oacc[dn * 2 + dh];
                    mma_bf16(o, ah,  vh4[2 * dh], vh4[2 * dh + 1]);
                    mma_bf16(o, alr, vh4[2 * dh], vh4[2 * dh + 1]);
                    mma_bf16(o, ah,  vl4[2 * dh], vl4[2 * dh + 1]);
                }
            }
        }
        __syncthreads();
    }

    // ---- epilogue: ctx hi/lo bf16 ----
    const float i0 = 1.f / l0, i1 = 1.f / l1;
    const size_t r0o = (size_t)(b * SQ + g0) * DM + h * DH;
    const size_t r1o = (size_t)(b * SQ + g1) * DM + h * DH;
#pragma unroll
    for (int nt = 0; nt < 8; ++nt) {
        int cb = (nt >> 1) * 16 + (nt & 1) * 8 + (lane & 3) * 2;
        uint32_t hi, lo;
        split2(oacc[nt][0] * i0, oacc[nt][1] * i0, hi, lo);
        *(uint32_t*)&g_chi[r0o + cb] = hi;
        *(uint32_t*)&g_clo[r0o + cb] = lo;
        split2(oacc[nt][2] * i1, oacc[nt][3] * i1, hi, lo);
        *(uint32_t*)&g_chi[r1o + cb] = hi;
        *(uint32_t*)&g_clo[r1o + cb] = lo;
    }
}

// ---------------- launch ----------------
extern "C" void kernel_launch(void* const* d_in, const int* in_sizes, int n_in,
                              void* d_out, int out_size)
{
    const float* x     = (const float*)d_in[0];
    const int*   amask = (const int*)  d_in[1];
    const float* Wqkv  = (const float*)d_in[2];
    const float* bqkv  = (const float*)d_in[3];
    const float* Aqkv  = (const float*)d_in[4];
    const float* Bqkv  = (const float*)d_in[5];
    const float* Wproj = (const float*)d_in[6];
    const float* bproj = (const float*)d_in[7];
    const float* Aproj = (const float*)d_in[8];
    const float* Bproj = (const float*)d_in[9];
    float* out = (float*)d_out;

    __nv_bfloat16 *qkvh, *qkvl, *xhi, *xlo, *whiT, *wloT, *phiT, *ploT, *chi, *clo;
    cudaGetSymbolAddress((void**)&qkvh, g_qkvh);
    cudaGetSymbolAddress((void**)&qkvl, g_qkvl);
    cudaGetSymbolAddress((void**)&xhi,  g_xhi);
    cudaGetSymbolAddress((void**)&xlo,  g_xlo);
    cudaGetSymbolAddress((void**)&whiT, g_whiT);
    cudaGetSymbolAddress((void**)&wloT, g_wloT);
    cudaGetSymbolAddress((void**)&phiT, g_phiT);
    cudaGetSymbolAddress((void**)&ploT, g_ploT);
    cudaGetSymbolAddress((void**)&chi,  g_chi);
    cudaGetSymbolAddress((void**)&clo,  g_clo);

    cudaFuncSetAttribute(mma_gemm_kernel, cudaFuncAttributeMaxDynamicSharedMemorySize, GSMEM);
    cudaFuncSetAttribute(flash_mma_kernel, cudaFuncAttributeMaxDynamicSharedMemorySize, FL_SMEM);

    // prep
    split_kernel<<<(MR * DM + 255) / 256, 256>>>(x, xhi, xlo, MR * DM);
    fold_split_T_kernel<<<dim3(N3 / 32, DM / 32), 256>>>(Wqkv,  Aqkv,  Bqkv,  whiT, wloT, N3, DM);
    fold_split_T_kernel<<<dim3(DM / 32, DM / 32), 256>>>(Wproj, Aproj, Bproj, phiT, ploT, DM, DM);

    // qkv = x @ W_eff + bias  -> bf16 hi/lo directly
    mma_gemm_kernel<<<dim3(N3 / 128, MR / 128), 256, GSMEM>>>(
        xhi, xlo, whiT, wloT, bqkv, nullptr, qkvh, qkvl, DM, N3, 1);

    // flash attention -> ctx hi/lo
    flash_mma_kernel<<<dim3(SQ / 128, NH, BB), 256, FL_SMEM>>>(amask);

    // out = ctx @ C_eff + bias (fp32 out)
    mma_gemm_kernel<<<dim3(DM / 128, MR / 128), 256, GSMEM>>>(
        chi, clo, phiT, ploT, bproj, out, nullptr, nullptr, DM, DM, 0);
}

// round 6
// speedup vs baseline: 3.3018x; 1.2190x over previous
#include <cuda_runtime.h>
#include <cuda_bf16.h>
#include <cuda_fp16.h>
#include <cstdint>

#define DM   1024
#define NH   16
#define DH   64
#define SQ   2048
#define BB   2
#define MR   (BB*SQ)      // 4096 token rows
#define N3   (3*DM)       // 3072
#define RANK 8
#define NEGBIG (-1.25e8f) // -1e9 / sqrt(64)

// ---------------- scratch (static __device__, no allocations) ----------------
__device__ __nv_bfloat16 g_qkvh[(size_t)MR * N3];   // qkv hi (bf16, for flash)
__device__ __nv_bfloat16 g_qkvl[(size_t)MR * N3];   // qkv lo
__device__ __half g_xhi [(size_t)MR * DM];          // x split fp16
__device__ __half g_xlo [(size_t)MR * DM];
__device__ __half g_whT [(size_t)N3 * DM];          // W_qkv^T fp16 (K contiguous)
__device__ __half g_phT [(size_t)DM * DM];          // c_proj^T fp16
__device__ __half g_chi [(size_t)MR * DM];          // ctx hi fp16
__device__ __half g_clo [(size_t)MR * DM];          // ctx lo fp16

// ============================ helpers ============================
__device__ __forceinline__ uint32_t smem_u32(const void* p) {
    uint32_t a;
    asm("{ .reg .u64 t; cvta.to.shared.u64 t, %1; cvt.u32.u64 %0, t; }" : "=r"(a) : "l"(p));
    return a;
}
__device__ __forceinline__ void cp16(uint32_t s, const void* g) {
    asm volatile("cp.async.cg.shared.global [%0], [%1], 16;" :: "r"(s), "l"(g));
}
#define CP_COMMIT() asm volatile("cp.async.commit_group;" ::: "memory")

__device__ __forceinline__ void ldm4(uint32_t& r0, uint32_t& r1, uint32_t& r2, uint32_t& r3,
                                     uint32_t addr) {
    asm volatile("ldmatrix.sync.aligned.m8n8.x4.shared.b16 {%0,%1,%2,%3}, [%4];"
                 : "=r"(r0), "=r"(r1), "=r"(r2), "=r"(r3) : "r"(addr));
}
__device__ __forceinline__ void ldm4t(uint32_t& r0, uint32_t& r1, uint32_t& r2, uint32_t& r3,
                                      uint32_t addr) {
    asm volatile("ldmatrix.sync.aligned.m8n8.x4.trans.shared.b16 {%0,%1,%2,%3}, [%4];"
                 : "=r"(r0), "=r"(r1), "=r"(r2), "=r"(r3) : "r"(addr));
}
__device__ __forceinline__ void mma_bf16(float* d, const uint32_t* a, uint32_t b0, uint32_t b1) {
    asm volatile("mma.sync.aligned.m16n8k16.row.col.f32.bf16.bf16.f32 "
                 "{%0,%1,%2,%3}, {%4,%5,%6,%7}, {%8,%9}, {%0,%1,%2,%3};"
                 : "+f"(d[0]), "+f"(d[1]), "+f"(d[2]), "+f"(d[3])
                 : "r"(a[0]), "r"(a[1]), "r"(a[2]), "r"(a[3]), "r"(b0), "r"(b1));
}
__device__ __forceinline__ void mma_f16(float* d, const uint32_t* a, uint32_t b0, uint32_t b1) {
    asm volatile("mma.sync.aligned.m16n8k16.row.col.f32.f16.f16.f32 "
                 "{%0,%1,%2,%3}, {%4,%5,%6,%7}, {%8,%9}, {%0,%1,%2,%3};"
                 : "+f"(d[0]), "+f"(d[1]), "+f"(d[2]), "+f"(d[3])
                 : "r"(a[0]), "r"(a[1]), "r"(a[2]), "r"(a[3]), "r"(b0), "r"(b1));
}
// bf16 hi/lo pack (for flash inputs)
__device__ __forceinline__ void split2b(float x, float y, uint32_t& hi, uint32_t& lo) {
    __nv_bfloat16 hx = __float2bfloat16(x), hy = __float2bfloat16(y);
    __nv_bfloat162 h2; h2.x = hx; h2.y = hy;
    __nv_bfloat162 l2;
    l2.x = __float2bfloat16(x - __bfloat162float(hx));
    l2.y = __float2bfloat16(y - __bfloat162float(hy));
    hi = *(uint32_t*)&h2; lo = *(uint32_t*)&l2;
}
// fp16 hi/lo pack (for GEMM activations)
__device__ __forceinline__ void split2h(float x, float y, uint32_t& hi, uint32_t& lo) {
    __half hx = __float2half_rn(x), hy = __float2half_rn(y);
    __half2 h2; h2.x = hx; h2.y = hy;
    __half2 l2;
    l2.x = __float2half_rn(x - __half2float(hx));
    l2.y = __float2half_rn(y - __half2float(hy));
    hi = *(uint32_t*)&h2; lo = *(uint32_t*)&l2;
}

// ================== prep: split fp32 -> fp16 hi/lo ==================
__global__ void split_kernel(const float* __restrict__ in,
                             __half* __restrict__ hi, __half* __restrict__ lo, int n)
{
    int i = blockIdx.x * 256 + threadIdx.x;
    if (i >= n) return;
    float v = in[i];
    __half h = __float2half_rn(v);
    hi[i] = h;
    lo[i] = __float2half_rn(v - __half2float(h));
}

// ====== prep: fold LoRA, round to fp16, transpose (K-contig rows) ======
__global__ __launch_bounds__(256) void fold_round_T_kernel(
    const float* __restrict__ W, const float* __restrict__ A, const float* __restrict__ Bm,
    __half* __restrict__ hT, int N, int K)
{
    __shared__ float sv[32][33];
    const int k0 = blockIdx.y * 32, n0 = blockIdx.x * 32;
    const int r = threadIdx.x >> 5, c = threadIdx.x & 31;
#pragma unroll
    for (int i = 0; i < 4; ++i) {
        int k = k0 + i * 8 + r, n = n0 + c;
        float s = 0.f;
#pragma unroll
        for (int rr = 0; rr < RANK; ++rr)
            s = fmaf(A[k * RANK + rr], Bm[rr * N + n], s);
        sv[i * 8 + r][c] = W[(size_t)k * N + n] + 2.0f * s;
    }
    __syncthreads();
#pragma unroll
    for (int i = 0; i < 4; ++i) {
        int n = n0 + i * 8 + r, k = k0 + c;
        hT[(size_t)n * K + k] = __float2half_rn(sv[c][i * 8 + r]);
    }
}

// ========== mma.sync fp16 GEMM (A exact 2-term, B rounded): C = A @ B^T + bias ==========
// 3-stage cp.async ring; tiles: Ah, Al, Bh (3 x 128 x 40 halves per stage)
#define BK 32
#define AST 40
#define TILE_ELT (128 * AST)          // 5120 halves = 10240 B
#define STAGE_ELT (3 * TILE_ELT)      // 30720 B
#define GSMEM (3 * STAGE_ELT * 2)     // 92160 B

__global__ __launch_bounds__(256) void mma_gemm_kernel(
    const __half* __restrict__ Ahi, const __half* __restrict__ Alo,
    const __half* __restrict__ Bh,
    const float* __restrict__ bias, float* __restrict__ C,
    __nv_bfloat16* __restrict__ Chi, __nv_bfloat16* __restrict__ Clo,
    int K, int N, int mode)
{
    extern __shared__ __half dsm[];
    const uint32_t sbase = smem_u32(dsm);

    const int tid = threadIdx.x, wid = tid >> 5, lane = tid & 31;
    const int row0 = blockIdx.y * 128, col0 = blockIdx.x * 128;
    const int wm = (wid & 1) * 64, wn = (wid >> 1) * 32;

    const __half* gsrc[3] = { Ahi, Alo, Bh };

    float acc[4][4][4] = {};

    const int a_row_l = wm + (lane & 15);
    const int a_k_l   = (lane >> 4) * 8;
    const int b_n_l   = wn + ((lane >> 3) & 1) * 8 + (lane & 7);
    const int b_k_l   = (lane >> 4) * 8;

    const int iters = K / BK;

    // stage loader: 1536 16B chunks -> 6 per thread
    auto load_stage = [&](int s, int k0) {
        const uint32_t sb = sbase + s * STAGE_ELT * 2;
#pragma unroll
        for (int t = 0; t < 6; ++t) {
            int idx = tid + t * 256;
            int a = idx >> 9, c = idx & 511;
            int r = c >> 2, kk = (c & 3) * 8;
            int grow = (a < 2 ? row0 : col0) + r;
            const __half* g = gsrc[a] + (size_t)grow * K + k0 + kk;
            cp16(sb + (a * TILE_ELT + r * AST + kk) * 2, g);
        }
    };

    load_stage(0, 0); CP_COMMIT();
    load_stage(1, BK); CP_COMMIT();

    for (int it = 0; it < iters; ++it) {
        asm volatile("cp.async.wait_group 1;" ::: "memory");
        __syncthreads();
        if (it + 2 < iters) {
            load_stage((it + 2) % 3, (it + 2) * BK);
            CP_COMMIT();
        }

        const uint32_t sb  = sbase + (it % 3) * STAGE_ELT * 2;
        const uint32_t bAh = sb;
        const uint32_t bAl = sb + TILE_ELT * 2;
        const uint32_t bBh = sb + 2 * TILE_ELT * 2;

#pragma unroll
        for (int ks = 0; ks < 2; ++ks) {
            uint32_t bh[2][4];
#pragma unroll
            for (int np = 0; np < 2; ++np) {
                uint32_t off = (uint32_t)((b_n_l + np * 16) * AST + ks * 16 + b_k_l) * 2;
                ldm4(bh[np][0], bh[np][1], bh[np][2], bh[np][3], bBh + off);
            }
#pragma unroll
            for (int mt = 0; mt < 4; ++mt) {
                uint32_t aoff = (uint32_t)((a_row_l + mt * 16) * AST + ks * 16 + a_k_l) * 2;
                uint32_t ah[4], al[4];
                ldm4(ah[0], ah[1], ah[2], ah[3], bAh + aoff);
                ldm4(al[0], al[1], al[2], al[3], bAl + aoff);
#pragma unroll
                for (int nt = 0; nt < 4; ++nt) {
                    const int np = nt >> 1, hh = nt & 1;
                    mma_f16(acc[mt][nt], ah, bh[np][hh], bh[np][2 + hh]);
                    mma_f16(acc[mt][nt], al, bh[np][hh], bh[np][2 + hh]);
                }
            }
        }
    }

#pragma unroll
    for (int mt = 0; mt < 4; ++mt) {
#pragma unroll
        for (int nt = 0; nt < 4; ++nt) {
            int rr = row0 + wm + mt * 16 + (lane >> 2);
            int cc = col0 + wn + nt * 8 + (lane & 3) * 2;
            float bx = bias[cc], by = bias[cc + 1];
            float v0 = acc[mt][nt][0] + bx, v1 = acc[mt][nt][1] + by;
            float v2 = acc[mt][nt][2] + bx, v3 = acc[mt][nt][3] + by;
            if (mode == 0) {
                *(float2*)&C[(size_t)rr * N + cc]       = make_float2(v0, v1);
                *(float2*)&C[(size_t)(rr + 8) * N + cc] = make_float2(v2, v3);
            } else {
                uint32_t hi, lo;
                split2b(v0, v1, hi, lo);
                *(uint32_t*)&Chi[(size_t)rr * N + cc] = hi;
                *(uint32_t*)&Clo[(size_t)rr * N + cc] = lo;
                split2b(v2, v3, hi, lo);
                *(uint32_t*)&Chi[(size_t)(rr + 8) * N + cc] = hi;
                *(uint32_t*)&Clo[(size_t)(rr + 8) * N + cc] = lo;
            }
        }
    }
}

// ============== flash attention, mma.sync bf16x3, BM=128 BN=64 ==============
#define FKST 72
#define Q_BYTES (128*FKST*2)                 // 18432
#define KV_BYTES (64*FKST*2)                 // 9216
#define STG_BYTES (4*KV_BYTES)               // 36864
#define MSK_OFF (2*Q_BYTES + 2*STG_BYTES)    // 110592
#define FL_SMEM (MSK_OFF + 512)

__global__ __launch_bounds__(256) void flash_mma_kernel(const int* __restrict__ amask)
{
    extern __shared__ char fsm[];
    const uint32_t sb = smem_u32(fsm);
    int* mskp = (int*)(fsm + MSK_OFF);

    const int qt = (gridDim.x - 1) - blockIdx.x;   // heavy tiles first
    const int h = blockIdx.y, b = blockIdx.z;
    const int tid = threadIdx.x, wid = tid >> 5, lane = tid & 31;
    const int q0 = qt * 128, wrow = wid * 16;

    auto load_q = [&]() {
#pragma unroll
        for (int t = 0; t < 8; ++t) {
            int idx = tid + t * 256;
            int a = idx >> 10, c = idx & 1023, r = c >> 3, ch = c & 7;
            const __nv_bfloat16* g = (a ? g_qkvl : g_qkvh)
                + (size_t)(b * SQ + q0 + r) * N3 + h * DH + ch * 8;
            cp16(sb + a * Q_BYTES + r * 144 + ch * 16, g);
        }
    };
    auto load_kv = [&](int s, int kb) {
        const uint32_t base = sb + 2 * Q_BYTES + s * STG_BYTES;
#pragma unroll
        for (int t = 0; t < 8; ++t) {
            int idx = tid + t * 256;
            int a = idx >> 9, c = idx & 511, r = c >> 3, ch = c & 7;
            const __nv_bfloat16* g = ((a & 1) ? g_qkvl : g_qkvh)
                + (size_t)(b * SQ + kb + r) * N3 + ((a >> 1) ? 2 * DM : DM) + h * DH + ch * 8;
            cp16(base + a * KV_BYTES + r * 144 + ch * 16, g);
        }
        if (tid < 64) mskp[s * 64 + tid] = amask[b * SQ + kb + tid];
    };

    load_q();
    load_kv(0, 0);
    CP_COMMIT();

    const int ktmax = 2 * qt + 1;
    float m0 = -1e30f, m1 = -1e30f, l0 = 0.f, l1 = 0.f;
    float oacc[8][4] = {};
    uint32_t qh[4][4], ql[4][4];

    const int arow = wrow + (lane & 15), ak2 = (lane >> 4) * 16;
    const int brow = ((lane >> 3) & 1) * 8 + (lane & 7), bk2 = (lane >> 4) * 16;
    const int vrow = ((lane >> 3) & 1) * 8 + (lane & 7);
    const int vcol = ((lane >> 4) & 1) * 16;
    const int g0 = q0 + wrow + (lane >> 2), g1 = g0 + 8;

    for (int kt = 0; kt <= ktmax; ++kt) {
        if (kt < ktmax) {
            load_kv((kt + 1) & 1, (kt + 1) * 64);
            CP_COMMIT();
            asm volatile("cp.async.wait_group 1;" ::: "memory");
        } else {
            asm volatile("cp.async.wait_group 0;" ::: "memory");
        }
        __syncthreads();

        if (kt == 0) {
#pragma unroll
            for (int ks = 0; ks < 4; ++ks) {
                uint32_t off = (uint32_t)(arow * 144 + ks * 32 + ak2);
                ldm4(qh[ks][0], qh[ks][1], qh[ks][2], qh[ks][3], sb + off);
                ldm4(ql[ks][0], ql[ks][1], ql[ks][2], ql[ks][3], sb + Q_BYTES + off);
            }
        }

        const uint32_t kh_b = sb + 2 * Q_BYTES + (kt & 1) * STG_BYTES;
        const uint32_t kl_b = kh_b + KV_BYTES;
        const uint32_t vh_b = kh_b + 2 * KV_BYTES;
        const uint32_t vl_b = kh_b + 3 * KV_BYTES;
        const int* msk = mskp + (kt & 1) * 64;
        const int kb = kt * 64;

        // ---- S = Q K^T (bf16x3) ----
        float sc[8][4] = {};
#pragma unroll
        for (int ks = 0; ks < 4; ++ks) {
#pragma unroll
            for (int np = 0; np < 4; ++np) {
                uint32_t kh4[4], kl4[4];
                uint32_t off = (uint32_t)((np * 16 + brow) * 144 + ks * 32 + bk2);
                ldm4(kh4[0], kh4[1], kh4[2], kh4[3], kh_b + off);
                ldm4(kl4[0], kl4[1], kl4[2], kl4[3], kl_b + off);
#pragma unroll
                for (int hh = 0; hh < 2; ++hh) {
                    float* d = sc[np * 2 + hh];
                    mma_bf16(d, qh[ks], kh4[hh], kh4[2 + hh]);
                    mma_bf16(d, qh[ks], kl4[hh], kl4[2 + hh]);
                    mma_bf16(d, ql[ks], kh4[hh], kh4[2 + hh]);
                }
            }
        }

        // ---- mask (causal + pad) then scale ----
#pragma unroll
        for (int nt = 0; nt < 8; ++nt) {
            int cb = (nt >> 1) * 16 + (nt & 1) * 8 + (lane & 3) * 2;
            int c0 = kb + cb;
            bool p0 = msk[cb] != 0, p1 = msk[cb + 1] != 0;
            sc[nt][0] = (!p0 || c0 > g0)     ? NEGBIG : sc[nt][0] * 0.125f;
            sc[nt][1] = (!p1 || c0 + 1 > g0) ? NEGBIG : sc[nt][1] * 0.125f;
            sc[nt][2] = (!p0 || c0 > g1)     ? NEGBIG : sc[nt][2] * 0.125f;
            sc[nt][3] = (!p1 || c0 + 1 > g1) ? NEGBIG : sc[nt][3] * 0.125f;
        }

        // ---- online softmax (rows g0, g1) ----
        float mx0 = -1e30f, mx1 = -1e30f;
#pragma unroll
        for (int nt = 0; nt < 8; ++nt) {
            mx0 = fmaxf(mx0, fmaxf(sc[nt][0], sc[nt][1]));
            mx1 = fmaxf(mx1, fmaxf(sc[nt][2], sc[nt][3]));
        }
        mx0 = fmaxf(mx0, __shfl_xor_sync(0xffffffffu, mx0, 1));
        mx0 = fmaxf(mx0, __shfl_xor_sync(0xffffffffu, mx0, 2));
        mx1 = fmaxf(mx1, __shfl_xor_sync(0xffffffffu, mx1, 1));
        mx1 = fmaxf(mx1, __shfl_xor_sync(0xffffffffu, mx1, 2));
        float mn0 = fmaxf(m0, mx0), mn1 = fmaxf(m1, mx1);
        float al0 = __expf(m0 - mn0), al1 = __expf(m1 - mn1);
        m0 = mn0; m1 = mn1;
        float sum0 = 0.f, sum1 = 0.f;
#pragma unroll
        for (int nt = 0; nt < 8; ++nt) {
            sc[nt][0] = __expf(sc[nt][0] - mn0);
            sc[nt][1] = __expf(sc[nt][1] - mn0);
            sc[nt][2] = __expf(sc[nt][2] - mn1);
            sc[nt][3] = __expf(sc[nt][3] - mn1);
            sum0 += sc[nt][0] + sc[nt][1];
            sum1 += sc[nt][2] + sc[nt][3];
        }
        sum0 += __shfl_xor_sync(0xffffffffu, sum0, 1);
        sum0 += __shfl_xor_sync(0xffffffffu, sum0, 2);
        sum1 += __shfl_xor_sync(0xffffffffu, sum1, 1);
        sum1 += __shfl_xor_sync(0xffffffffu, sum1, 2);
        l0 = l0 * al0 + sum0;
        l1 = l1 * al1 + sum1;
#pragma unroll
        for (int nt = 0; nt < 8; ++nt) {
            oacc[nt][0] *= al0; oacc[nt][1] *= al0;
            oacc[nt][2] *= al1; oacc[nt][3] *= al1;
        }

        // ---- O += P V (bf16x3); V trans pairs (r[2*dh], r[2*dh+1]) ----
#pragma unroll
        for (int ks2 = 0; ks2 < 4; ++ks2) {
            uint32_t ah[4], alr[4];
            split2b(sc[2 * ks2][0],     sc[2 * ks2][1],     ah[0], alr[0]);
            split2b(sc[2 * ks2][2],     sc[2 * ks2][3],     ah[1], alr[1]);
            split2b(sc[2 * ks2 + 1][0], sc[2 * ks2 + 1][1], ah[2], alr[2]);
            split2b(sc[2 * ks2 + 1][2], sc[2 * ks2 + 1][3], ah[3], alr[3]);
#pragma unroll
            for (int dn = 0; dn < 4; ++dn) {
                uint32_t vh4[4], vl4[4];
                uint32_t voff = (uint32_t)((ks2 * 16 + vrow) * 144 + dn * 32 + vcol);
                ldm4t(vh4[0], vh4[1], vh4[2], vh4[3], vh_b + voff);
                ldm4t(vl4[0], vl4[1], vl4[2], vl4[3], vl_b + voff);
#pragma unroll
                for (int dh = 0; dh < 2; ++dh) {
                    float* o = oacc[dn * 2 + dh];
                    mma_bf16(o, ah,  vh4[2 * dh], vh4[2 * dh + 1]);
                    mma_bf16(o, alr, vh4[2 * dh], vh4[2 * dh + 1]);
                    mma_bf16(o, ah,  vl4[2 * dh], vl4[2 * dh + 1]);
                }
            }
        }
        __syncthreads();
    }

    // ---- epilogue: ctx hi/lo fp16 (feeds fp16 proj GEMM) ----
    const float i0 = 1.f / l0, i1 = 1.f / l1;
    const size_t r0o = (size_t)(b * SQ + g0) * DM + h * DH;
    const size_t r1o = (size_t)(b * SQ + g1) * DM + h * DH;
#pragma unroll
    for (int nt = 0; nt < 8; ++nt) {
        int cb = (nt >> 1) * 16 + (nt & 1) * 8 + (lane & 3) * 2;
        uint32_t hi, lo;
        split2h(oacc[nt][0] * i0, oacc[nt][1] * i0, hi, lo);
        *(uint32_t*)&g_chi[r0o + cb] = hi;
        *(uint32_t*)&g_clo[r0o + cb] = lo;
        split2h(oacc[nt][2] * i1, oacc[nt][3] * i1, hi, lo);
        *(uint32_t*)&g_chi[r1o + cb] = hi;
        *(uint32_t*)&g_clo[r1o + cb] = lo;
    }
}

// ---------------- launch ----------------
extern "C" void kernel_launch(void* const* d_in, const int* in_sizes, int n_in,
                              void* d_out, int out_size)
{
    const float* x     = (const float*)d_in[0];
    const int*   amask = (const int*)  d_in[1];
    const float* Wqkv  = (const float*)d_in[2];
    const float* bqkv  = (const float*)d_in[3];
    const float* Aqkv  = (const float*)d_in[4];
    const float* Bqkv  = (const float*)d_in[5];
    const float* Wproj = (const float*)d_in[6];
    const float* bproj = (const float*)d_in[7];
    const float* Aproj = (const float*)d_in[8];
    const float* Bproj = (const float*)d_in[9];
    float* out = (float*)d_out;

    __nv_bfloat16 *qkvh, *qkvl;
    __half *xhi, *xlo, *whT, *phT, *chi, *clo;
    cudaGetSymbolAddress((void**)&qkvh, g_qkvh);
    cudaGetSymbolAddress((void**)&qkvl, g_qkvl);
    cudaGetSymbolAddress((void**)&xhi,  g_xhi);
    cudaGetSymbolAddress((void**)&xlo,  g_xlo);
    cudaGetSymbolAddress((void**)&whT,  g_whT);
    cudaGetSymbolAddress((void**)&phT,  g_phT);
    cudaGetSymbolAddress((void**)&chi,  g_chi);
    cudaGetSymbolAddress((void**)&clo,  g_clo);

    cudaFuncSetAttribute(mma_gemm_kernel, cudaFuncAttributeMaxDynamicSharedMemorySize, GSMEM);
    cudaFuncSetAttribute(flash_mma_kernel, cudaFuncAttributeMaxDynamicSharedMemorySize, FL_SMEM);

    // prep
    split_kernel<<<(MR * DM + 255) / 256, 256>>>(x, xhi, xlo, MR * DM);
    fold_round_T_kernel<<<dim3(N3 / 32, DM / 32), 256>>>(Wqkv,  Aqkv,  Bqkv,  whT, N3, DM);
    fold_round_T_kernel<<<dim3(DM / 32, DM / 32), 256>>>(Wproj, Aproj, Bproj, phT, DM, DM);

    // qkv = x @ W_eff + bias  -> bf16 hi/lo for flash
    mma_gemm_kernel<<<dim3(N3 / 128, MR / 128), 256, GSMEM>>>(
        xhi, xlo, whT, bqkv, nullptr, qkvh, qkvl, DM, N3, 1);

    // flash attention -> ctx hi/lo (fp16)
    flash_mma_kernel<<<dim3(SQ / 128, NH, BB), 256, FL_SMEM>>>(amask);

    // out = ctx @ C_eff + bias (fp32 out)
    mma_gemm_kernel<<<dim3(DM / 128, MR / 128), 256, GSMEM>>>(
        chi, clo, phT, bproj, out, nullptr, nullptr, DM, DM, 0);
}

// round 7
// speedup vs baseline: 3.8639x; 1.1702x over previous
#include <cuda_runtime.h>
#include <cuda_bf16.h>
#include <cuda_fp16.h>
#include <cstdint>

#define DM   1024
#define NH   16
#define DH   64
#define SQ   2048
#define BB   2
#define MR   (BB*SQ)      // 4096 token rows
#define N3   (3*DM)       // 3072
#define RANK 8
#define NEGBIG (-1.25e8f) // -1e9 / sqrt(64)

// ---------------- scratch (static __device__, no allocations) ----------------
__device__ __half g_qkvh[(size_t)MR * N3];   // qkv hi fp16
__device__ __half g_qkvl[(size_t)MR * N3];   // qkv lo fp16 (only Q part used)
__device__ __half g_xhi [(size_t)MR * DM];
__device__ __half g_xlo [(size_t)MR * DM];
__device__ __half g_whT [(size_t)N3 * DM];   // W_qkv^T fp16 (K contiguous)
__device__ __half g_phT [(size_t)DM * DM];   // c_proj^T fp16
__device__ __half g_chi [(size_t)MR * DM];   // ctx hi fp16
__device__ __half g_clo [(size_t)MR * DM];   // ctx lo fp16

// ============================ helpers ============================
__device__ __forceinline__ uint32_t smem_u32(const void* p) {
    uint32_t a;
    asm("{ .reg .u64 t; cvta.to.shared.u64 t, %1; cvt.u32.u64 %0, t; }" : "=r"(a) : "l"(p));
    return a;
}
__device__ __forceinline__ void cp16(uint32_t s, const void* g) {
    asm volatile("cp.async.cg.shared.global [%0], [%1], 16;" :: "r"(s), "l"(g));
}
#define CP_COMMIT() asm volatile("cp.async.commit_group;" ::: "memory")

__device__ __forceinline__ void ldm4(uint32_t& r0, uint32_t& r1, uint32_t& r2, uint32_t& r3,
                                     uint32_t addr) {
    asm volatile("ldmatrix.sync.aligned.m8n8.x4.shared.b16 {%0,%1,%2,%3}, [%4];"
                 : "=r"(r0), "=r"(r1), "=r"(r2), "=r"(r3) : "r"(addr));
}
__device__ __forceinline__ void ldm4t(uint32_t& r0, uint32_t& r1, uint32_t& r2, uint32_t& r3,
                                      uint32_t addr) {
    asm volatile("ldmatrix.sync.aligned.m8n8.x4.trans.shared.b16 {%0,%1,%2,%3}, [%4];"
                 : "=r"(r0), "=r"(r1), "=r"(r2), "=r"(r3) : "r"(addr));
}
__device__ __forceinline__ void mma_f16(float* d, const uint32_t* a, uint32_t b0, uint32_t b1) {
    asm volatile("mma.sync.aligned.m16n8k16.row.col.f32.f16.f16.f32 "
                 "{%0,%1,%2,%3}, {%4,%5,%6,%7}, {%8,%9}, {%0,%1,%2,%3};"
                 : "+f"(d[0]), "+f"(d[1]), "+f"(d[2]), "+f"(d[3])
                 : "r"(a[0]), "r"(a[1]), "r"(a[2]), "r"(a[3]), "r"(b0), "r"(b1));
}
// fp16 hi/lo pack
__device__ __forceinline__ void split2h(float x, float y, uint32_t& hi, uint32_t& lo) {
    __half hx = __float2half_rn(x), hy = __float2half_rn(y);
    __half2 h2; h2.x = hx; h2.y = hy;
    __half2 l2;
    l2.x = __float2half_rn(x - __half2float(hx));
    l2.y = __float2half_rn(y - __half2float(hy));
    hi = *(uint32_t*)&h2; lo = *(uint32_t*)&l2;
}

// ================== prep: split fp32 -> fp16 hi/lo ==================
__global__ void split_kernel(const float* __restrict__ in,
                             __half* __restrict__ hi, __half* __restrict__ lo, int n)
{
    int i = blockIdx.x * 256 + threadIdx.x;
    if (i >= n) return;
    float v = in[i];
    __half h = __float2half_rn(v);
    hi[i] = h;
    lo[i] = __float2half_rn(v - __half2float(h));
}

// ====== prep: fold LoRA, round to fp16, transpose (K-contig rows) ======
__global__ __launch_bounds__(256) void fold_round_T_kernel(
    const float* __restrict__ W, const float* __restrict__ A, const float* __restrict__ Bm,
    __half* __restrict__ hT, int N, int K)
{
    __shared__ float sv[32][33];
    const int k0 = blockIdx.y * 32, n0 = blockIdx.x * 32;
    const int r = threadIdx.x >> 5, c = threadIdx.x & 31;
#pragma unroll
    for (int i = 0; i < 4; ++i) {
        int k = k0 + i * 8 + r, n = n0 + c;
        float s = 0.f;
#pragma unroll
        for (int rr = 0; rr < RANK; ++rr)
            s = fmaf(A[k * RANK + rr], Bm[rr * N + n], s);
        sv[i * 8 + r][c] = W[(size_t)k * N + n] + 2.0f * s;
    }
    __syncthreads();
#pragma unroll
    for (int i = 0; i < 4; ++i) {
        int n = n0 + i * 8 + r, k = k0 + c;
        hT[(size_t)n * K + k] = __float2half_rn(sv[c][i * 8 + r]);
    }
}

// ========== mma.sync fp16 GEMM (A exact 2-term, B rounded): C = A @ B^T + bias ==========
#define BK 32
#define AST 40
#define TILE_ELT (128 * AST)          // 5120 halves
#define STAGE_ELT (3 * TILE_ELT)
#define GSMEM (3 * STAGE_ELT * 2)     // 92160 B

__global__ __launch_bounds__(256) void mma_gemm_kernel(
    const __half* __restrict__ Ahi, const __half* __restrict__ Alo,
    const __half* __restrict__ Bh,
    const float* __restrict__ bias, float* __restrict__ C,
    __half* __restrict__ Chi, __half* __restrict__ Clo,
    int K, int N, int mode)
{
    extern __shared__ __half dsm[];
    const uint32_t sbase = smem_u32(dsm);

    const int tid = threadIdx.x, wid = tid >> 5, lane = tid & 31;
    const int row0 = blockIdx.y * 128, col0 = blockIdx.x * 128;
    const int wm = (wid & 1) * 64, wn = (wid >> 1) * 32;

    const __half* gsrc[3] = { Ahi, Alo, Bh };

    float acc[4][4][4] = {};

    const int a_row_l = wm + (lane & 15);
    const int a_k_l   = (lane >> 4) * 8;
    const int b_n_l   = wn + ((lane >> 3) & 1) * 8 + (lane & 7);
    const int b_k_l   = (lane >> 4) * 8;

    const int iters = K / BK;

    auto load_stage = [&](int s, int k0) {
        const uint32_t sb = sbase + s * STAGE_ELT * 2;
#pragma unroll
        for (int t = 0; t < 6; ++t) {
            int idx = tid + t * 256;
            int a = idx >> 9, c = idx & 511;
            int r = c >> 2, kk = (c & 3) * 8;
            int grow = (a < 2 ? row0 : col0) + r;
            const __half* g = gsrc[a] + (size_t)grow * K + k0 + kk;
            cp16(sb + (a * TILE_ELT + r * AST + kk) * 2, g);
        }
    };

    load_stage(0, 0); CP_COMMIT();
    load_stage(1, BK); CP_COMMIT();

    for (int it = 0; it < iters; ++it) {
        asm volatile("cp.async.wait_group 1;" ::: "memory");
        __syncthreads();
        if (it + 2 < iters) {
            load_stage((it + 2) % 3, (it + 2) * BK);
            CP_COMMIT();
        }

        const uint32_t sb  = sbase + (it % 3) * STAGE_ELT * 2;
        const uint32_t bAh = sb;
        const uint32_t bAl = sb + TILE_ELT * 2;
        const uint32_t bBh = sb + 2 * TILE_ELT * 2;

#pragma unroll
        for (int ks = 0; ks < 2; ++ks) {
            uint32_t bh[2][4];
#pragma unroll
            for (int np = 0; np < 2; ++np) {
                uint32_t off = (uint32_t)((b_n_l + np * 16) * AST + ks * 16 + b_k_l) * 2;
                ldm4(bh[np][0], bh[np][1], bh[np][2], bh[np][3], bBh + off);
            }
#pragma unroll
            for (int mt = 0; mt < 4; ++mt) {
                uint32_t aoff = (uint32_t)((a_row_l + mt * 16) * AST + ks * 16 + a_k_l) * 2;
                uint32_t ah[4], al[4];
                ldm4(ah[0], ah[1], ah[2], ah[3], bAh + aoff);
                ldm4(al[0], al[1], al[2], al[3], bAl + aoff);
#pragma unroll
                for (int nt = 0; nt < 4; ++nt) {
                    const int np = nt >> 1, hh = nt & 1;
                    mma_f16(acc[mt][nt], ah, bh[np][hh], bh[np][2 + hh]);
                    mma_f16(acc[mt][nt], al, bh[np][hh], bh[np][2 + hh]);
                }
            }
        }
    }

#pragma unroll
    for (int mt = 0; mt < 4; ++mt) {
#pragma unroll
        for (int nt = 0; nt < 4; ++nt) {
            int rr = row0 + wm + mt * 16 + (lane >> 2);
            int cc = col0 + wn + nt * 8 + (lane & 3) * 2;
            float bx = bias[cc], by = bias[cc + 1];
            float v0 = acc[mt][nt][0] + bx, v1 = acc[mt][nt][1] + by;
            float v2 = acc[mt][nt][2] + bx, v3 = acc[mt][nt][3] + by;
            if (mode == 0) {
                *(float2*)&C[(size_t)rr * N + cc]       = make_float2(v0, v1);
                *(float2*)&C[(size_t)(rr + 8) * N + cc] = make_float2(v2, v3);
            } else {
                uint32_t hi, lo;
                split2h(v0, v1, hi, lo);
                *(uint32_t*)&Chi[(size_t)rr * N + cc] = hi;
                *(uint32_t*)&Clo[(size_t)rr * N + cc] = lo;
                split2h(v2, v3, hi, lo);
                *(uint32_t*)&Chi[(size_t)(rr + 8) * N + cc] = hi;
                *(uint32_t*)&Clo[(size_t)(rr + 8) * N + cc] = lo;
            }
        }
    }
}

// ============== flash attention, mma.sync fp16 2-term, BM=128 BN=64 ==============
// Q exact (hi+lo fp16), K/V rounded single fp16. S: 2 mma, PV: 2 mma.
#define FKST 72
#define Q_BYTES (128*FKST*2)                 // 18432
#define KV_BYTES (64*FKST*2)                 // 9216
#define STG_BYTES (2*KV_BYTES)               // 18432 (K + V)
#define MSK_OFF (2*Q_BYTES + 2*STG_BYTES)    // 73728
#define FL_SMEM (MSK_OFF + 512)

__global__ __launch_bounds__(256) void flash_mma_kernel(const int* __restrict__ amask)
{
    extern __shared__ char fsm[];
    const uint32_t sb = smem_u32(fsm);
    int* mskp = (int*)(fsm + MSK_OFF);

    const int qt = (gridDim.x - 1) - blockIdx.x;   // heavy tiles first
    const int h = blockIdx.y, b = blockIdx.z;
    const int tid = threadIdx.x, wid = tid >> 5, lane = tid & 31;
    const int q0 = qt * 128, wrow = wid * 16;

    auto load_q = [&]() {
#pragma unroll
        for (int t = 0; t < 8; ++t) {
            int idx = tid + t * 256;
            int a = idx >> 10, c = idx & 1023, r = c >> 3, ch = c & 7;
            const __half* g = (a ? g_qkvl : g_qkvh)
                + (size_t)(b * SQ + q0 + r) * N3 + h * DH + ch * 8;
            cp16(sb + a * Q_BYTES + r * 144 + ch * 16, g);
        }
    };
    auto load_kv = [&](int s, int kb) {
        const uint32_t base = sb + 2 * Q_BYTES + s * STG_BYTES;
#pragma unroll
        for (int t = 0; t < 4; ++t) {
            int idx = tid + t * 256;
            int a = idx >> 9, c = idx & 511, r = c >> 3, ch = c & 7;
            const __half* g = g_qkvh
                + (size_t)(b * SQ + kb + r) * N3 + (a ? 2 * DM : DM) + h * DH + ch * 8;
            cp16(base + a * KV_BYTES + r * 144 + ch * 16, g);
        }
        if (tid < 64) mskp[s * 64 + tid] = amask[b * SQ + kb + tid];
    };

    load_q();
    load_kv(0, 0);
    CP_COMMIT();

    const int ktmax = 2 * qt + 1;
    float m0 = -1e30f, m1 = -1e30f, l0 = 0.f, l1 = 0.f;
    float oacc[8][4] = {};
    uint32_t qh[4][4], ql[4][4];

    const int arow = wrow + (lane & 15), ak2 = (lane >> 4) * 16;
    const int brow = ((lane >> 3) & 1) * 8 + (lane & 7), bk2 = (lane >> 4) * 16;
    const int vrow = ((lane >> 3) & 1) * 8 + (lane & 7);
    const int vcol = ((lane >> 4) & 1) * 16;
    const int g0 = q0 + wrow + (lane >> 2), g1 = g0 + 8;

    for (int kt = 0; kt <= ktmax; ++kt) {
        if (kt < ktmax) {
            load_kv((kt + 1) & 1, (kt + 1) * 64);
            CP_COMMIT();
            asm volatile("cp.async.wait_group 1;" ::: "memory");
        } else {
            asm volatile("cp.async.wait_group 0;" ::: "memory");
        }
        __syncthreads();

        if (kt == 0) {
#pragma unroll
            for (int ks = 0; ks < 4; ++ks) {
                uint32_t off = (uint32_t)(arow * 144 + ks * 32 + ak2);
                ldm4(qh[ks][0], qh[ks][1], qh[ks][2], qh[ks][3], sb + off);
                ldm4(ql[ks][0], ql[ks][1], ql[ks][2], ql[ks][3], sb + Q_BYTES + off);
            }
        }

        const uint32_t kh_b = sb + 2 * Q_BYTES + (kt & 1) * STG_BYTES;
        const uint32_t vh_b = kh_b + KV_BYTES;
        const int* msk = mskp + (kt & 1) * 64;
        const int kb = kt * 64;

        // ---- S = Q K^T (fp16, Q 2-term) ----
        float sc[8][4] = {};
#pragma unroll
        for (int ks = 0; ks < 4; ++ks) {
#pragma unroll
            for (int np = 0; np < 4; ++np) {
                uint32_t kh4[4];
                uint32_t off = (uint32_t)((np * 16 + brow) * 144 + ks * 32 + bk2);
                ldm4(kh4[0], kh4[1], kh4[2], kh4[3], kh_b + off);
#pragma unroll
                for (int hh = 0; hh < 2; ++hh) {
                    float* d = sc[np * 2 + hh];
                    mma_f16(d, qh[ks], kh4[hh], kh4[2 + hh]);
                    mma_f16(d, ql[ks], kh4[hh], kh4[2 + hh]);
                }
            }
        }

        // ---- mask (causal + pad) then scale ----
#pragma unroll
        for (int nt = 0; nt < 8; ++nt) {
            int cb = (nt >> 1) * 16 + (nt & 1) * 8 + (lane & 3) * 2;
            int c0 = kb + cb;
            bool p0 = msk[cb] != 0, p1 = msk[cb + 1] != 0;
            sc[nt][0] = (!p0 || c0 > g0)     ? NEGBIG : sc[nt][0] * 0.125f;
            sc[nt][1] = (!p1 || c0 + 1 > g0) ? NEGBIG : sc[nt][1] * 0.125f;
            sc[nt][2] = (!p0 || c0 > g1)     ? NEGBIG : sc[nt][2] * 0.125f;
            sc[nt][3] = (!p1 || c0 + 1 > g1) ? NEGBIG : sc[nt][3] * 0.125f;
        }

        // ---- online softmax (rows g0, g1) ----
        float mx0 = -1e30f, mx1 = -1e30f;
#pragma unroll
        for (int nt = 0; nt < 8; ++nt) {
            mx0 = fmaxf(mx0, fmaxf(sc[nt][0], sc[nt][1]));
            mx1 = fmaxf(mx1, fmaxf(sc[nt][2], sc[nt][3]));
        }
        mx0 = fmaxf(mx0, __shfl_xor_sync(0xffffffffu, mx0, 1));
        mx0 = fmaxf(mx0, __shfl_xor_sync(0xffffffffu, mx0, 2));
        mx1 = fmaxf(mx1, __shfl_xor_sync(0xffffffffu, mx1, 1));
        mx1 = fmaxf(mx1, __shfl_xor_sync(0xffffffffu, mx1, 2));
        float mn0 = fmaxf(m0, mx0), mn1 = fmaxf(m1, mx1);
        float al0 = __expf(m0 - mn0), al1 = __expf(m1 - mn1);
        m0 = mn0; m1 = mn1;
        float sum0 = 0.f, sum1 = 0.f;
#pragma unroll
        for (int nt = 0; nt < 8; ++nt) {
            sc[nt][0] = __expf(sc[nt][0] - mn0);
            sc[nt][1] = __expf(sc[nt][1] - mn0);
            sc[nt][2] = __expf(sc[nt][2] - mn1);
            sc[nt][3] = __expf(sc[nt][3] - mn1);
            sum0 += sc[nt][0] + sc[nt][1];
            sum1 += sc[nt][2] + sc[nt][3];
        }
        sum0 += __shfl_xor_sync(0xffffffffu, sum0, 1);
        sum0 += __shfl_xor_sync(0xffffffffu, sum0, 2);
        sum1 += __shfl_xor_sync(0xffffffffu, sum1, 1);
        sum1 += __shfl_xor_sync(0xffffffffu, sum1, 2);
        l0 = l0 * al0 + sum0;
        l1 = l1 * al1 + sum1;
#pragma unroll
        for (int nt = 0; nt < 8; ++nt) {
            oacc[nt][0] *= al0; oacc[nt][1] *= al0;
            oacc[nt][2] *= al1; oacc[nt][3] *= al1;
        }

        // ---- O += P V (fp16, P exact 2-term); V trans pairs (r[2*dh], r[2*dh+1]) ----
#pragma unroll
        for (int ks2 = 0; ks2 < 4; ++ks2) {
            uint32_t ph[4], pl[4];
            split2h(sc[2 * ks2][0],     sc[2 * ks2][1],     ph[0], pl[0]);
            split2h(sc[2 * ks2][2],     sc[2 * ks2][3],     ph[1], pl[1]);
            split2h(sc[2 * ks2 + 1][0], sc[2 * ks2 + 1][1], ph[2], pl[2]);
            split2h(sc[2 * ks2 + 1][2], sc[2 * ks2 + 1][3], ph[3], pl[3]);
#pragma unroll
            for (int dn = 0; dn < 4; ++dn) {
                uint32_t vh4[4];
                uint32_t voff = (uint32_t)((ks2 * 16 + vrow) * 144 + dn * 32 + vcol);
                ldm4t(vh4[0], vh4[1], vh4[2], vh4[3], vh_b + voff);
#pragma unroll
                for (int dh = 0; dh < 2; ++dh) {
                    float* o = oacc[dn * 2 + dh];
                    mma_f16(o, ph, vh4[2 * dh], vh4[2 * dh + 1]);
                    mma_f16(o, pl, vh4[2 * dh], vh4[2 * dh + 1]);
                }
            }
        }
        __syncthreads();
    }

    // ---- epilogue: ctx hi/lo fp16 ----
    const float i0 = 1.f / l0, i1 = 1.f / l1;
    const size_t r0o = (size_t)(b * SQ + g0) * DM + h * DH;
    const size_t r1o = (size_t)(b * SQ + g1) * DM + h * DH;
#pragma unroll
    for (int nt = 0; nt < 8; ++nt) {
        int cb = (nt >> 1) * 16 + (nt & 1) * 8 + (lane & 3) * 2;
        uint32_t hi, lo;
        split2h(oacc[nt][0] * i0, oacc[nt][1] * i0, hi, lo);
        *(uint32_t*)&g_chi[r0o + cb] = hi;
        *(uint32_t*)&g_clo[r0o + cb] = lo;
        split2h(oacc[nt][2] * i1, oacc[nt][3] * i1, hi, lo);
        *(uint32_t*)&g_chi[r1o + cb] = hi;
        *(uint32_t*)&g_clo[r1o + cb] = lo;
    }
}

// ---------------- launch ----------------
extern "C" void kernel_launch(void* const* d_in, const int* in_sizes, int n_in,
                              void* d_out, int out_size)
{
    const float* x     = (const float*)d_in[0];
    const int*   amask = (const int*)  d_in[1];
    const float* Wqkv  = (const float*)d_in[2];
    const float* bqkv  = (const float*)d_in[3];
    const float* Aqkv  = (const float*)d_in[4];
    const float* Bqkv  = (const float*)d_in[5];
    const float* Wproj = (const float*)d_in[6];
    const float* bproj = (const float*)d_in[7];
    const float* Aproj = (const float*)d_in[8];
    const float* Bproj = (const float*)d_in[9];
    float* out = (float*)d_out;

    __half *qkvh, *qkvl, *xhi, *xlo, *whT, *phT, *chi, *clo;
    cudaGetSymbolAddress((void**)&qkvh, g_qkvh);
    cudaGetSymbolAddress((void**)&qkvl, g_qkvl);
    cudaGetSymbolAddress((void**)&xhi,  g_xhi);
    cudaGetSymbolAddress((void**)&xlo,  g_xlo);
    cudaGetSymbolAddress((void**)&whT,  g_whT);
    cudaGetSymbolAddress((void**)&phT,  g_phT);
    cudaGetSymbolAddress((void**)&chi,  g_chi);
    cudaGetSymbolAddress((void**)&clo,  g_clo);

    cudaFuncSetAttribute(mma_gemm_kernel, cudaFuncAttributeMaxDynamicSharedMemorySize, GSMEM);
    cudaFuncSetAttribute(flash_mma_kernel, cudaFuncAttributeMaxDynamicSharedMemorySize, FL_SMEM);

    // prep
    split_kernel<<<(MR * DM + 255) / 256, 256>>>(x, xhi, xlo, MR * DM);
    fold_round_T_kernel<<<dim3(N3 / 32, DM / 32), 256>>>(Wqkv,  Aqkv,  Bqkv,  whT, N3, DM);
    fold_round_T_kernel<<<dim3(DM / 32, DM / 32), 256>>>(Wproj, Aproj, Bproj, phT, DM, DM);

    // qkv = x @ W_eff + bias  -> fp16 hi/lo
    mma_gemm_kernel<<<dim3(N3 / 128, MR / 128), 256, GSMEM>>>(
        xhi, xlo, whT, bqkv, nullptr, qkvh, qkvl, DM, N3, 1);

    // flash attention -> ctx hi/lo (fp16)
    flash_mma_kernel<<<dim3(SQ / 128, NH, BB), 256, FL_SMEM>>>(amask);

    // out = ctx @ C_eff + bias (fp32 out)
    mma_gemm_kernel<<<dim3(DM / 128, MR / 128), 256, GSMEM>>>(
        chi, clo, phT, bproj, out, nullptr, nullptr, DM, DM, 0);
}

// round 8
// speedup vs baseline: 4.1127x; 1.0644x over previous
#include <cuda_runtime.h>
#include <cuda_bf16.h>
#include <cuda_fp16.h>
#include <cstdint>

#define DM   1024
#define NH   16
#define DH   64
#define SQ   2048
#define BB   2
#define MR   (BB*SQ)      // 4096 token rows
#define N3   (3*DM)       // 3072
#define RANK 8
#define NEGBIG (-1.25e8f) // -1e9 / sqrt(64)

// ---------------- scratch (static __device__, no allocations) ----------------
__device__ __half g_qkvh[(size_t)MR * N3];   // qkv hi fp16
__device__ __half g_qkvl[(size_t)MR * N3];   // qkv lo fp16 (only Q part consumed)
__device__ __half g_xh  [(size_t)MR * DM];   // x rounded fp16
__device__ __half g_whT [(size_t)N3 * DM];   // W_qkv^T fp16 (K contiguous)
__device__ __half g_phT [(size_t)DM * DM];   // c_proj^T fp16
__device__ __half g_ch  [(size_t)MR * DM];   // ctx rounded fp16

// ============================ helpers ============================
__device__ __forceinline__ uint32_t smem_u32(const void* p) {
    uint32_t a;
    asm("{ .reg .u64 t; cvta.to.shared.u64 t, %1; cvt.u32.u64 %0, t; }" : "=r"(a) : "l"(p));
    return a;
}
__device__ __forceinline__ void cp16(uint32_t s, const void* g) {
    asm volatile("cp.async.cg.shared.global [%0], [%1], 16;" :: "r"(s), "l"(g));
}
#define CP_COMMIT() asm volatile("cp.async.commit_group;" ::: "memory")

__device__ __forceinline__ void ldm4(uint32_t& r0, uint32_t& r1, uint32_t& r2, uint32_t& r3,
                                     uint32_t addr) {
    asm volatile("ldmatrix.sync.aligned.m8n8.x4.shared.b16 {%0,%1,%2,%3}, [%4];"
                 : "=r"(r0), "=r"(r1), "=r"(r2), "=r"(r3) : "r"(addr));
}
__device__ __forceinline__ void ldm4t(uint32_t& r0, uint32_t& r1, uint32_t& r2, uint32_t& r3,
                                      uint32_t addr) {
    asm volatile("ldmatrix.sync.aligned.m8n8.x4.trans.shared.b16 {%0,%1,%2,%3}, [%4];"
                 : "=r"(r0), "=r"(r1), "=r"(r2), "=r"(r3) : "r"(addr));
}
__device__ __forceinline__ void mma_f16(float* d, const uint32_t* a, uint32_t b0, uint32_t b1) {
    asm volatile("mma.sync.aligned.m16n8k16.row.col.f32.f16.f16.f32 "
                 "{%0,%1,%2,%3}, {%4,%5,%6,%7}, {%8,%9}, {%0,%1,%2,%3};"
                 : "+f"(d[0]), "+f"(d[1]), "+f"(d[2]), "+f"(d[3])
                 : "r"(a[0]), "r"(a[1]), "r"(a[2]), "r"(a[3]), "r"(b0), "r"(b1));
}
// fp16 hi/lo pack
__device__ __forceinline__ void split2h(float x, float y, uint32_t& hi, uint32_t& lo) {
    __half hx = __float2half_rn(x), hy = __float2half_rn(y);
    __half2 h2; h2.x = hx; h2.y = hy;
    __half2 l2;
    l2.x = __float2half_rn(x - __half2float(hx));
    l2.y = __float2half_rn(y - __half2float(hy));
    hi = *(uint32_t*)&h2; lo = *(uint32_t*)&l2;
}
__device__ __forceinline__ uint32_t pack2h(float x, float y) {
    __half2 h2; h2.x = __float2half_rn(x); h2.y = __float2half_rn(y);
    return *(uint32_t*)&h2;
}

// ================== prep: round fp32 -> fp16 ==================
__global__ void round_kernel(const float* __restrict__ in, __half* __restrict__ h, int n)
{
    int i = blockIdx.x * 256 + threadIdx.x;
    if (i >= n) return;
    h[i] = __float2half_rn(in[i]);
}

// ====== prep: fold LoRA, round to fp16, transpose (K-contig rows) ======
__global__ __launch_bounds__(256) void fold_round_T_kernel(
    const float* __restrict__ W, const float* __restrict__ A, const float* __restrict__ Bm,
    __half* __restrict__ hT, int N, int K)
{
    __shared__ float sv[32][33];
    const int k0 = blockIdx.y * 32, n0 = blockIdx.x * 32;
    const int r = threadIdx.x >> 5, c = threadIdx.x & 31;
#pragma unroll
    for (int i = 0; i < 4; ++i) {
        int k = k0 + i * 8 + r, n = n0 + c;
        float s = 0.f;
#pragma unroll
        for (int rr = 0; rr < RANK; ++rr)
            s = fmaf(A[k * RANK + rr], Bm[rr * N + n], s);
        sv[i * 8 + r][c] = W[(size_t)k * N + n] + 2.0f * s;
    }
    __syncthreads();
#pragma unroll
    for (int i = 0; i < 4; ++i) {
        int n = n0 + i * 8 + r, k = k0 + c;
        hT[(size_t)n * K + k] = __float2half_rn(sv[c][i * 8 + r]);
    }
}

// ========== mma.sync fp16 1-term GEMM: C = A @ B^T + bias ==========
// A row-major [M x K] fp16; B transposed [N x K] fp16. CTA 128x128, BK=32, 3-stage ring.
#define BK 32
#define AST 40
#define TILE_ELT (128 * AST)          // 5120 halves = 10240 B
#define STAGE_ELT (2 * TILE_ELT)      // A + B
#define GSMEM (3 * STAGE_ELT * 2)     // 61440 B

__global__ __launch_bounds__(256, 3) void mma_gemm_kernel(
    const __half* __restrict__ A, const __half* __restrict__ B,
    const float* __restrict__ bias, float* __restrict__ C,
    __half* __restrict__ Chi, __half* __restrict__ Clo,
    int K, int N, int mode)
{
    extern __shared__ __half dsm[];
    const uint32_t sbase = smem_u32(dsm);

    const int tid = threadIdx.x, wid = tid >> 5, lane = tid & 31;
    const int row0 = blockIdx.y * 128, col0 = blockIdx.x * 128;
    const int wm = (wid & 1) * 64, wn = (wid >> 1) * 32;

    float acc[4][4][4] = {};

    const int a_row_l = wm + (lane & 15);
    const int a_k_l   = (lane >> 4) * 8;
    const int b_n_l   = wn + ((lane >> 3) & 1) * 8 + (lane & 7);
    const int b_k_l   = (lane >> 4) * 8;

    const int iters = K / BK;

    // stage loader: 1024 chunks of 16B -> 4 per thread
    auto load_stage = [&](int s, int k0) {
        const uint32_t sb = sbase + s * STAGE_ELT * 2;
#pragma unroll
        for (int t = 0; t < 4; ++t) {
            int idx = tid + t * 256;
            int a = idx >> 9, c = idx & 511;
            int r = c >> 2, kk = (c & 3) * 8;
            const __half* g = (a ? B + (size_t)(col0 + r) * K : A + (size_t)(row0 + r) * K)
                              + k0 + kk;
            cp16(sb + (a * TILE_ELT + r * AST + kk) * 2, g);
        }
    };

    load_stage(0, 0); CP_COMMIT();
    load_stage(1, BK); CP_COMMIT();

    for (int it = 0; it < iters; ++it) {
        asm volatile("cp.async.wait_group 1;" ::: "memory");
        __syncthreads();
        if (it + 2 < iters) {
            load_stage((it + 2) % 3, (it + 2) * BK);
            CP_COMMIT();
        }

        const uint32_t sb  = sbase + (it % 3) * STAGE_ELT * 2;
        const uint32_t bA = sb;
        const uint32_t bB = sb + TILE_ELT * 2;

#pragma unroll
        for (int ks = 0; ks < 2; ++ks) {
            uint32_t bh[2][4];
#pragma unroll
            for (int np = 0; np < 2; ++np) {
                uint32_t off = (uint32_t)((b_n_l + np * 16) * AST + ks * 16 + b_k_l) * 2;
                ldm4(bh[np][0], bh[np][1], bh[np][2], bh[np][3], bB + off);
            }
#pragma unroll
            for (int mt = 0; mt < 4; ++mt) {
                uint32_t aoff = (uint32_t)((a_row_l + mt * 16) * AST + ks * 16 + a_k_l) * 2;
                uint32_t ah[4];
                ldm4(ah[0], ah[1], ah[2], ah[3], bA + aoff);
#pragma unroll
                for (int nt = 0; nt < 4; ++nt) {
                    const int np = nt >> 1, hh = nt & 1;
                    mma_f16(acc[mt][nt], ah, bh[np][hh], bh[np][2 + hh]);
                }
            }
        }
    }

#pragma unroll
    for (int mt = 0; mt < 4; ++mt) {
#pragma unroll
        for (int nt = 0; nt < 4; ++nt) {
            int rr = row0 + wm + mt * 16 + (lane >> 2);
            int cc = col0 + wn + nt * 8 + (lane & 3) * 2;
            float bx = bias[cc], by = bias[cc + 1];
            float v0 = acc[mt][nt][0] + bx, v1 = acc[mt][nt][1] + by;
            float v2 = acc[mt][nt][2] + bx, v3 = acc[mt][nt][3] + by;
            if (mode == 0) {
                *(float2*)&C[(size_t)rr * N + cc]       = make_float2(v0, v1);
                *(float2*)&C[(size_t)(rr + 8) * N + cc] = make_float2(v2, v3);
            } else {
                uint32_t hi, lo;
                split2h(v0, v1, hi, lo);
                *(uint32_t*)&Chi[(size_t)rr * N + cc] = hi;
                *(uint32_t*)&Clo[(size_t)rr * N + cc] = lo;
                split2h(v2, v3, hi, lo);
                *(uint32_t*)&Chi[(size_t)(rr + 8) * N + cc] = hi;
                *(uint32_t*)&Clo[(size_t)(rr + 8) * N + cc] = lo;
            }
        }
    }
}

// ============== flash attention, mma.sync fp16, BM=128 BN=64 ==============
// Q exact (hi+lo fp16), K/V rounded single fp16. S: 2 mma, PV: 2 mma (P exact 2-term).
#define FKST 72
#define Q_BYTES (128*FKST*2)                 // 18432
#define KV_BYTES (64*FKST*2)                 // 9216
#define STG_BYTES (2*KV_BYTES)               // 18432 (K + V)
#define MSK_OFF (2*Q_BYTES + 2*STG_BYTES)    // 73728
#define FL_SMEM (MSK_OFF + 512)

__global__ __launch_bounds__(256) void flash_mma_kernel(const int* __restrict__ amask)
{
    extern __shared__ char fsm[];
    const uint32_t sb = smem_u32(fsm);
    int* mskp = (int*)(fsm + MSK_OFF);

    const int qt = (gridDim.x - 1) - blockIdx.x;   // heavy tiles first
    const int h = blockIdx.y, b = blockIdx.z;
    const int tid = threadIdx.x, wid = tid >> 5, lane = tid & 31;
    const int q0 = qt * 128, wrow = wid * 16;

    auto load_q = [&]() {
#pragma unroll
        for (int t = 0; t < 8; ++t) {
            int idx = tid + t * 256;
            int a = idx >> 10, c = idx & 1023, r = c >> 3, ch = c & 7;
            const __half* g = (a ? g_qkvl : g_qkvh)
                + (size_t)(b * SQ + q0 + r) * N3 + h * DH + ch * 8;
            cp16(sb + a * Q_BYTES + r * 144 + ch * 16, g);
        }
    };
    auto load_kv = [&](int s, int kb) {
        const uint32_t base = sb + 2 * Q_BYTES + s * STG_BYTES;
#pragma unroll
        for (int t = 0; t < 4; ++t) {
            int idx = tid + t * 256;
            int a = idx >> 9, c = idx & 511, r = c >> 3, ch = c & 7;
            const __half* g = g_qkvh
                + (size_t)(b * SQ + kb + r) * N3 + (a ? 2 * DM : DM) + h * DH + ch * 8;
            cp16(base + a * KV_BYTES + r * 144 + ch * 16, g);
        }
        if (tid < 64) mskp[s * 64 + tid] = amask[b * SQ + kb + tid];
    };

    load_q();
    load_kv(0, 0);
    CP_COMMIT();

    const int ktmax = 2 * qt + 1;
    float m0 = -1e30f, m1 = -1e30f, l0 = 0.f, l1 = 0.f;
    float oacc[8][4] = {};
    uint32_t qh[4][4], ql[4][4];

    const int arow = wrow + (lane & 15), ak2 = (lane >> 4) * 16;
    const int brow = ((lane >> 3) & 1) * 8 + (lane & 7), bk2 = (lane >> 4) * 16;
    const int vrow = ((lane >> 3) & 1) * 8 + (lane & 7);
    const int vcol = ((lane >> 4) & 1) * 16;
    const int g0 = q0 + wrow + (lane >> 2), g1 = g0 + 8;

    for (int kt = 0; kt <= ktmax; ++kt) {
        if (kt < ktmax) {
            load_kv((kt + 1) & 1, (kt + 1) * 64);
            CP_COMMIT();
            asm volatile("cp.async.wait_group 1;" ::: "memory");
        } else {
            asm volatile("cp.async.wait_group 0;" ::: "memory");
        }
        __syncthreads();

        if (kt == 0) {
#pragma unroll
            for (int ks = 0; ks < 4; ++ks) {
                uint32_t off = (uint32_t)(arow * 144 + ks * 32 + ak2);
                ldm4(qh[ks][0], qh[ks][1], qh[ks][2], qh[ks][3], sb + off);
                ldm4(ql[ks][0], ql[ks][1], ql[ks][2], ql[ks][3], sb + Q_BYTES + off);
            }
        }

        const uint32_t kh_b = sb + 2 * Q_BYTES + (kt & 1) * STG_BYTES;
        const uint32_t vh_b = kh_b + KV_BYTES;
        const int* msk = mskp + (kt & 1) * 64;
        const int kb = kt * 64;

        // ---- S = Q K^T (fp16, Q 2-term) ----
        float sc[8][4] = {};
#pragma unroll
        for (int ks = 0; ks < 4; ++ks) {
#pragma unroll
            for (int np = 0; np < 4; ++np) {
                uint32_t kh4[4];
                uint32_t off = (uint32_t)((np * 16 + brow) * 144 + ks * 32 + bk2);
                ldm4(kh4[0], kh4[1], kh4[2], kh4[3], kh_b + off);
#pragma unroll
                for (int hh = 0; hh < 2; ++hh) {
                    float* d = sc[np * 2 + hh];
                    mma_f16(d, qh[ks], kh4[hh], kh4[2 + hh]);
                    mma_f16(d, ql[ks], kh4[hh], kh4[2 + hh]);
                }
            }
        }

        // ---- mask (causal + pad) then scale ----
#pragma unroll
        for (int nt = 0; nt < 8; ++nt) {
            int cb = (nt >> 1) * 16 + (nt & 1) * 8 + (lane & 3) * 2;
            int c0 = kb + cb;
            bool p0 = msk[cb] != 0, p1 = msk[cb + 1] != 0;
            sc[nt][0] = (!p0 || c0 > g0)     ? NEGBIG : sc[nt][0] * 0.125f;
            sc[nt][1] = (!p1 || c0 + 1 > g0) ? NEGBIG : sc[nt][1] * 0.125f;
            sc[nt][2] = (!p0 || c0 > g1)     ? NEGBIG : sc[nt][2] * 0.125f;
            sc[nt][3] = (!p1 || c0 + 1 > g1) ? NEGBIG : sc[nt][3] * 0.125f;
        }

        // ---- online softmax (rows g0, g1) ----
        float mx0 = -1e30f, mx1 = -1e30f;
#pragma unroll
        for (int nt = 0; nt < 8; ++nt) {
            mx0 = fmaxf(mx0, fmaxf(sc[nt][0], sc[nt][1]));
            mx1 = fmaxf(mx1, fmaxf(sc[nt][2], sc[nt][3]));
        }
        mx0 = fmaxf(mx0, __shfl_xor_sync(0xffffffffu, mx0, 1));
        mx0 = fmaxf(mx0, __shfl_xor_sync(0xffffffffu, mx0, 2));
        mx1 = fmaxf(mx1, __shfl_xor_sync(0xffffffffu, mx1, 1));
        mx1 = fmaxf(mx1, __shfl_xor_sync(0xffffffffu, mx1, 2));
        float mn0 = fmaxf(m0, mx0), mn1 = fmaxf(m1, mx1);
        float al0 = __expf(m0 - mn0), al1 = __expf(m1 - mn1);
        m0 = mn0; m1 = mn1;
        float sum0 = 0.f, sum1 = 0.f;
#pragma unroll
        for (int nt = 0; nt < 8; ++nt) {
            sc[nt][0] = __expf(sc[nt][0] - mn0);
            sc[nt][1] = __expf(sc[nt][1] - mn0);
            sc[nt][2] = __expf(sc[nt][2] - mn1);
            sc[nt][3] = __expf(sc[nt][3] - mn1);
            sum0 += sc[nt][0] + sc[nt][1];
            sum1 += sc[nt][2] + sc[nt][3];
        }
        sum0 += __shfl_xor_sync(0xffffffffu, sum0, 1);
        sum0 += __shfl_xor_sync(0xffffffffu, sum0, 2);
        sum1 += __shfl_xor_sync(0xffffffffu, sum1, 1);
        sum1 += __shfl_xor_sync(0xffffffffu, sum1, 2);
        l0 = l0 * al0 + sum0;
        l1 = l1 * al1 + sum1;
#pragma unroll
        for (int nt = 0; nt < 8; ++nt) {
            oacc[nt][0] *= al0; oacc[nt][1] *= al0;
            oacc[nt][2] *= al1; oacc[nt][3] *= al1;
        }

        // ---- O += P V (fp16, P exact 2-term); V trans pairs (r[2*dh], r[2*dh+1]) ----
#pragma unroll
        for (int ks2 = 0; ks2 < 4; ++ks2) {
            uint32_t ph[4], pl[4];
            split2h(sc[2 * ks2][0],     sc[2 * ks2][1],     ph[0], pl[0]);
            split2h(sc[2 * ks2][2],     sc[2 * ks2][3],     ph[1], pl[1]);
            split2h(sc[2 * ks2 + 1][0], sc[2 * ks2 + 1][1], ph[2], pl[2]);
            split2h(sc[2 * ks2 + 1][2], sc[2 * ks2 + 1][3], ph[3], pl[3]);
#pragma unroll
            for (int dn = 0; dn < 4; ++dn) {
                uint32_t vh4[4];
                uint32_t voff = (uint32_t)((ks2 * 16 + vrow) * 144 + dn * 32 + vcol);
                ldm4t(vh4[0], vh4[1], vh4[2], vh4[3], vh_b + voff);
#pragma unroll
                for (int dh = 0; dh < 2; ++dh) {
                    float* o = oacc[dn * 2 + dh];
                    mma_f16(o, ph, vh4[2 * dh], vh4[2 * dh + 1]);
                    mma_f16(o, pl, vh4[2 * dh], vh4[2 * dh + 1]);
                }
            }
        }
        __syncthreads();
    }

    // ---- epilogue: ctx rounded fp16 (single term) ----
    const float i0 = 1.f / l0, i1 = 1.f / l1;
    const size_t r0o = (size_t)(b * SQ + g0) * DM + h * DH;
    const size_t r1o = (size_t)(b * SQ + g1) * DM + h * DH;
#pragma unroll
    for (int nt = 0; nt < 8; ++nt) {
        int cb = (nt >> 1) * 16 + (nt & 1) * 8 + (lane & 3) * 2;
        *(uint32_t*)&g_ch[r0o + cb] = pack2h(oacc[nt][0] * i0, oacc[nt][1] * i0);
        *(uint32_t*)&g_ch[r1o + cb] = pack2h(oacc[nt][2] * i1, oacc[nt][3] * i1);
    }
}

// ---------------- launch ----------------
extern "C" void kernel_launch(void* const* d_in, const int* in_sizes, int n_in,
                              void* d_out, int out_size)
{
    const float* x     = (const float*)d_in[0];
    const int*   amask = (const int*)  d_in[1];
    const float* Wqkv  = (const float*)d_in[2];
    const float* bqkv  = (const float*)d_in[3];
    const float* Aqkv  = (const float*)d_in[4];
    const float* Bqkv  = (const float*)d_in[5];
    const float* Wproj = (const float*)d_in[6];
    const float* bproj = (const float*)d_in[7];
    const float* Aproj = (const float*)d_in[8];
    const float* Bproj = (const float*)d_in[9];
    float* out = (float*)d_out;

    __half *qkvh, *qkvl, *xh, *whT, *phT, *ch;
    cudaGetSymbolAddress((void**)&qkvh, g_qkvh);
    cudaGetSymbolAddress((void**)&qkvl, g_qkvl);
    cudaGetSymbolAddress((void**)&xh,   g_xh);
    cudaGetSymbolAddress((void**)&whT,  g_whT);
    cudaGetSymbolAddress((void**)&phT,  g_phT);
    cudaGetSymbolAddress((void**)&ch,   g_ch);

    cudaFuncSetAttribute(mma_gemm_kernel, cudaFuncAttributeMaxDynamicSharedMemorySize, GSMEM);
    cudaFuncSetAttribute(flash_mma_kernel, cudaFuncAttributeMaxDynamicSharedMemorySize, FL_SMEM);

    // prep
    round_kernel<<<(MR * DM + 255) / 256, 256>>>(x, xh, MR * DM);
    fold_round_T_kernel<<<dim3(N3 / 32, DM / 32), 256>>>(Wqkv,  Aqkv,  Bqkv,  whT, N3, DM);
    fold_round_T_kernel<<<dim3(DM / 32, DM / 32), 256>>>(Wproj, Aproj, Bproj, phT, DM, DM);

    // qkv = x @ W_eff + bias  -> fp16 hi/lo (Q uses both, K/V use hi)
    mma_gemm_kernel<<<dim3(N3 / 128, MR / 128), 256, GSMEM>>>(
        xh, whT, bqkv, nullptr, qkvh, qkvl, DM, N3, 1);

    // flash attention -> ctx fp16
    flash_mma_kernel<<<dim3(SQ / 128, NH, BB), 256, FL_SMEM>>>(amask);

    // out = ctx @ C_eff + bias (fp32 out)
    mma_gemm_kernel<<<dim3(DM / 128, MR / 128), 256, GSMEM>>>(
        ch, phT, bproj, out, nullptr, nullptr, DM, DM, 0);
}

// round 9
// speedup vs baseline: 4.9316x; 1.1991x over previous
#include <cuda_runtime.h>
#include <cuda_bf16.h>
#include <cuda_fp16.h>
#include <cstdint>

#define DM   1024
#define NH   16
#define DH   64
#define SQ   2048
#define BB   2
#define MR   (BB*SQ)      // 4096 token rows
#define N3   (3*DM)       // 3072
#define RANK 8
#define NEGBIG (-1.25e8f) // -1e9 / sqrt(64)

// ---------------- scratch (static __device__, no allocations) ----------------
__device__ __half g_qkvh[(size_t)MR * N3];   // qkv hi fp16
__device__ __half g_qkvl[(size_t)MR * N3];   // qkv lo fp16 (only Q third written/consumed)
__device__ __half g_xh  [(size_t)MR * DM];   // x rounded fp16
__device__ __half g_whT [(size_t)N3 * DM];   // W_qkv^T fp16 (K contiguous)
__device__ __half g_phT [(size_t)DM * DM];   // c_proj^T fp16
__device__ __half g_ch  [(size_t)MR * DM];   // ctx rounded fp16

// ============================ helpers ============================
__device__ __forceinline__ uint32_t smem_u32(const void* p) {
    uint32_t a;
    asm("{ .reg .u64 t; cvta.to.shared.u64 t, %1; cvt.u32.u64 %0, t; }" : "=r"(a) : "l"(p));
    return a;
}
__device__ __forceinline__ void cp16(uint32_t s, const void* g) {
    asm volatile("cp.async.cg.shared.global [%0], [%1], 16;" :: "r"(s), "l"(g));
}
#define CP_COMMIT() asm volatile("cp.async.commit_group;" ::: "memory")

__device__ __forceinline__ void ldm4(uint32_t& r0, uint32_t& r1, uint32_t& r2, uint32_t& r3,
                                     uint32_t addr) {
    asm volatile("ldmatrix.sync.aligned.m8n8.x4.shared.b16 {%0,%1,%2,%3}, [%4];"
                 : "=r"(r0), "=r"(r1), "=r"(r2), "=r"(r3) : "r"(addr));
}
__device__ __forceinline__ void ldm4t(uint32_t& r0, uint32_t& r1, uint32_t& r2, uint32_t& r3,
                                      uint32_t addr) {
    asm volatile("ldmatrix.sync.aligned.m8n8.x4.trans.shared.b16 {%0,%1,%2,%3}, [%4];"
                 : "=r"(r0), "=r"(r1), "=r"(r2), "=r"(r3) : "r"(addr));
}
__device__ __forceinline__ void mma_f16(float* d, const uint32_t* a, uint32_t b0, uint32_t b1) {
    asm volatile("mma.sync.aligned.m16n8k16.row.col.f32.f16.f16.f32 "
                 "{%0,%1,%2,%3}, {%4,%5,%6,%7}, {%8,%9}, {%0,%1,%2,%3};"
                 : "+f"(d[0]), "+f"(d[1]), "+f"(d[2]), "+f"(d[3])
                 : "r"(a[0]), "r"(a[1]), "r"(a[2]), "r"(a[3]), "r"(b0), "r"(b1));
}
// fp16 hi/lo pack
__device__ __forceinline__ void split2h(float x, float y, uint32_t& hi, uint32_t& lo) {
    __half hx = __float2half_rn(x), hy = __float2half_rn(y);
    __half2 h2; h2.x = hx; h2.y = hy;
    __half2 l2;
    l2.x = __float2half_rn(x - __half2float(hx));
    l2.y = __float2half_rn(y - __half2float(hy));
    hi = *(uint32_t*)&h2; lo = *(uint32_t*)&l2;
}
__device__ __forceinline__ uint32_t pack2h(float x, float y) {
    __half2 h2; h2.x = __float2half_rn(x); h2.y = __float2half_rn(y);
    return *(uint32_t*)&h2;
}

// ================== prep: round fp32 -> fp16 ==================
__global__ void round_kernel(const float* __restrict__ in, __half* __restrict__ h, int n)
{
    int i = blockIdx.x * 256 + threadIdx.x;
    if (i >= n) return;
    h[i] = __float2half_rn(in[i]);
}

// ====== prep: fold LoRA, round to fp16, transpose (K-contig rows) ======
__global__ __launch_bounds__(256) void fold_round_T_kernel(
    const float* __restrict__ W, const float* __restrict__ A, const float* __restrict__ Bm,
    __half* __restrict__ hT, int N, int K)
{
    __shared__ float sv[32][33];
    const int k0 = blockIdx.y * 32, n0 = blockIdx.x * 32;
    const int r = threadIdx.x >> 5, c = threadIdx.x & 31;
#pragma unroll
    for (int i = 0; i < 4; ++i) {
        int k = k0 + i * 8 + r, n = n0 + c;
        float s = 0.f;
#pragma unroll
        for (int rr = 0; rr < RANK; ++rr)
            s = fmaf(A[k * RANK + rr], Bm[rr * N + n], s);
        sv[i * 8 + r][c] = W[(size_t)k * N + n] + 2.0f * s;
    }
    __syncthreads();
#pragma unroll
    for (int i = 0; i < 4; ++i) {
        int n = n0 + i * 8 + r, k = k0 + c;
        hT[(size_t)n * K + k] = __float2half_rn(sv[c][i * 8 + r]);
    }
}

// ========== mma.sync fp16 GEMM: C = A @ B^T + bias ==========
// CTA tile 128(M) x 256(N), 8 warps (2x4), warp tile 64x64. BK=32, 4-stage cp.async ring.
#define BK 32
#define AST 40
#define TILE_A (128 * AST)            // 5120 halves
#define TILE_B (256 * AST)            // 10240 halves
#define STAGE_ELT (TILE_A + TILE_B)   // 15360 halves = 30720 B
#define NSTG 4
#define GSMEM (NSTG * STAGE_ELT * 2)  // 122880 B

__global__ __launch_bounds__(256) void mma_gemm_kernel(
    const __half* __restrict__ A, const __half* __restrict__ B,
    const float* __restrict__ bias, float* __restrict__ C,
    __half* __restrict__ Chi, __half* __restrict__ Clo,
    int K, int N, int mode)
{
    extern __shared__ __half dsm[];
    const uint32_t sbase = smem_u32(dsm);

    const int tid = threadIdx.x, wid = tid >> 5, lane = tid & 31;
    const int row0 = blockIdx.y * 128, col0 = blockIdx.x * 256;
    const int wm = (wid >> 2) * 64, wn = (wid & 3) * 64;

    float acc[4][8][4] = {};

    const int a_row_l = wm + (lane & 15);
    const int a_k_l   = (lane >> 4) * 8;
    const int b_n_l   = wn + ((lane >> 3) & 1) * 8 + (lane & 7);
    const int b_k_l   = (lane >> 4) * 8;

    const int iters = K / BK;

    // stage loader: A 512 + B 1024 chunks of 16B -> 6 per thread
    auto load_stage = [&](int s, int k0) {
        const uint32_t sb = sbase + s * STAGE_ELT * 2;
#pragma unroll
        for (int t = 0; t < 6; ++t) {
            int idx = tid + t * 256;
            if (idx < 512) {
                int r = idx >> 2, kk = (idx & 3) * 8;
                cp16(sb + (r * AST + kk) * 2, A + (size_t)(row0 + r) * K + k0 + kk);
            } else {
                int i2 = idx - 512;
                int r = i2 >> 2, kk = (i2 & 3) * 8;
                cp16(sb + (TILE_A + r * AST + kk) * 2, B + (size_t)(col0 + r) * K + k0 + kk);
            }
        }
    };

    load_stage(0, 0); CP_COMMIT();
    load_stage(1, BK); CP_COMMIT();
    load_stage(2, 2 * BK); CP_COMMIT();

    for (int it = 0; it < iters; ++it) {
        asm volatile("cp.async.wait_group 2;" ::: "memory");
        __syncthreads();
        if (it + 3 < iters) load_stage((it + 3) & (NSTG - 1), (it + 3) * BK);
        CP_COMMIT();   // unconditional: keeps pending-group count invariant (no tail race)

        const uint32_t sb = sbase + (it & (NSTG - 1)) * STAGE_ELT * 2;
        const uint32_t bA = sb;
        const uint32_t bB = sb + TILE_A * 2;

#pragma unroll
        for (int ks = 0; ks < 2; ++ks) {
            uint32_t bh[4][4];
#pragma unroll
            for (int np = 0; np < 4; ++np) {
                uint32_t off = (uint32_t)((b_n_l + np * 16) * AST + ks * 16 + b_k_l) * 2;
                ldm4(bh[np][0], bh[np][1], bh[np][2], bh[np][3], bB + off);
            }
#pragma unroll
            for (int mt = 0; mt < 4; ++mt) {
                uint32_t aoff = (uint32_t)((a_row_l + mt * 16) * AST + ks * 16 + a_k_l) * 2;
                uint32_t ah[4];
                ldm4(ah[0], ah[1], ah[2], ah[3], bA + aoff);
#pragma unroll
                for (int nt = 0; nt < 8; ++nt) {
                    const int np = nt >> 1, hh = nt & 1;
                    mma_f16(acc[mt][nt], ah, bh[np][hh], bh[np][2 + hh]);
                }
            }
        }
    }

#pragma unroll
    for (int mt = 0; mt < 4; ++mt) {
#pragma unroll
        for (int nt = 0; nt < 8; ++nt) {
            int rr = row0 + wm + mt * 16 + (lane >> 2);
            int cc = col0 + wn + nt * 8 + (lane & 3) * 2;
            float bx = bias[cc], by = bias[cc + 1];
            float v0 = acc[mt][nt][0] + bx, v1 = acc[mt][nt][1] + by;
            float v2 = acc[mt][nt][2] + bx, v3 = acc[mt][nt][3] + by;
            if (mode == 0) {
                *(float2*)&C[(size_t)rr * N + cc]       = make_float2(v0, v1);
                *(float2*)&C[(size_t)(rr + 8) * N + cc] = make_float2(v2, v3);
            } else {
                uint32_t hi, lo;
                split2h(v0, v1, hi, lo);
                *(uint32_t*)&Chi[(size_t)rr * N + cc] = hi;
                if (cc < DM) *(uint32_t*)&Clo[(size_t)rr * N + cc] = lo;
                split2h(v2, v3, hi, lo);
                *(uint32_t*)&Chi[(size_t)(rr + 8) * N + cc] = hi;
                if (cc < DM) *(uint32_t*)&Clo[(size_t)(rr + 8) * N + cc] = lo;
            }
        }
    }
}

// ============== flash attention, mma.sync fp16, BM=128 BN=64 ==============
// Q exact (hi+lo fp16), K/V rounded single fp16. S: 2 mma, PV: 2 mma (P exact 2-term).
#define FKST 72
#define Q_BYTES (128*FKST*2)                 // 18432
#define KV_BYTES (64*FKST*2)                 // 9216
#define STG_BYTES (2*KV_BYTES)               // 18432 (K + V)
#define MSK_OFF (2*Q_BYTES + 2*STG_BYTES)    // 73728
#define FL_SMEM (MSK_OFF + 512)

__global__ __launch_bounds__(256) void flash_mma_kernel(const int* __restrict__ amask)
{
    extern __shared__ char fsm[];
    const uint32_t sb = smem_u32(fsm);
    int* mskp = (int*)(fsm + MSK_OFF);

    const int qt = (gridDim.x - 1) - blockIdx.x;   // heavy tiles first
    const int h = blockIdx.y, b = blockIdx.z;
    const int tid = threadIdx.x, wid = tid >> 5, lane = tid & 31;
    const int q0 = qt * 128, wrow = wid * 16;

    auto load_q = [&]() {
#pragma unroll
        for (int t = 0; t < 8; ++t) {
            int idx = tid + t * 256;
            int a = idx >> 10, c = idx & 1023, r = c >> 3, ch = c & 7;
            const __half* g = (a ? g_qkvl : g_qkvh)
                + (size_t)(b * SQ + q0 + r) * N3 + h * DH + ch * 8;
            cp16(sb + a * Q_BYTES + r * 144 + ch * 16, g);
        }
    };
    auto load_kv = [&](int s, int kb) {
        const uint32_t base = sb + 2 * Q_BYTES + s * STG_BYTES;
#pragma unroll
        for (int t = 0; t < 4; ++t) {
            int idx = tid + t * 256;
            int a = idx >> 9, c = idx & 511, r = c >> 3, ch = c & 7;
            const __half* g = g_qkvh
                + (size_t)(b * SQ + kb + r) * N3 + (a ? 2 * DM : DM) + h * DH + ch * 8;
            cp16(base + a * KV_BYTES + r * 144 + ch * 16, g);
        }
        if (tid < 64) mskp[s * 64 + tid] = amask[b * SQ + kb + tid];
    };

    load_q();
    load_kv(0, 0);
    CP_COMMIT();

    const int ktmax = 2 * qt + 1;
    float m0 = -1e30f, m1 = -1e30f, l0 = 0.f, l1 = 0.f;
    float oacc[8][4] = {};
    uint32_t qh[4][4], ql[4][4];

    const int arow = wrow + (lane & 15), ak2 = (lane >> 4) * 16;
    const int brow = ((lane >> 3) & 1) * 8 + (lane & 7), bk2 = (lane >> 4) * 16;
    const int vrow = ((lane >> 3) & 1) * 8 + (lane & 7);
    const int vcol = ((lane >> 4) & 1) * 16;
    const int g0 = q0 + wrow + (lane >> 2), g1 = g0 + 8;

    for (int kt = 0; kt <= ktmax; ++kt) {
        if (kt < ktmax) {
            load_kv((kt + 1) & 1, (kt + 1) * 64);
            CP_COMMIT();
            asm volatile("cp.async.wait_group 1;" ::: "memory");
        } else {
            asm volatile("cp.async.wait_group 0;" ::: "memory");
        }
        __syncthreads();

        if (kt == 0) {
#pragma unroll
            for (int ks = 0; ks < 4; ++ks) {
                uint32_t off = (uint32_t)(arow * 144 + ks * 32 + ak2);
                ldm4(qh[ks][0], qh[ks][1], qh[ks][2], qh[ks][3], sb + off);
                ldm4(ql[ks][0], ql[ks][1], ql[ks][2], ql[ks][3], sb + Q_BYTES + off);
            }
        }

        const uint32_t kh_b = sb + 2 * Q_BYTES + (kt & 1) * STG_BYTES;
        const uint32_t vh_b = kh_b + KV_BYTES;
        const int* msk = mskp + (kt & 1) * 64;
        const int kb = kt * 64;

        // ---- S = Q K^T (fp16, Q 2-term) ----
        float sc[8][4] = {};
#pragma unroll
        for (int ks = 0; ks < 4; ++ks) {
#pragma unroll
            for (int np = 0; np < 4; ++np) {
                uint32_t kh4[4];
                uint32_t off = (uint32_t)((np * 16 + brow) * 144 + ks * 32 + bk2);
                ldm4(kh4[0], kh4[1], kh4[2], kh4[3], kh_b + off);
#pragma unroll
                for (int hh = 0; hh < 2; ++hh) {
                    float* d = sc[np * 2 + hh];
                    mma_f16(d, qh[ks], kh4[hh], kh4[2 + hh]);
                    mma_f16(d, ql[ks], kh4[hh], kh4[2 + hh]);
                }
            }
        }

        // ---- mask (causal + pad) then scale ----
#pragma unroll
        for (int nt = 0; nt < 8; ++nt) {
            int cb = (nt >> 1) * 16 + (nt & 1) * 8 + (lane & 3) * 2;
            int c0 = kb + cb;
            bool p0 = msk[cb] != 0, p1 = msk[cb + 1] != 0;
            sc[nt][0] = (!p0 || c0 > g0)     ? NEGBIG : sc[nt][0] * 0.125f;
            sc[nt][1] = (!p1 || c0 + 1 > g0) ? NEGBIG : sc[nt][1] * 0.125f;
            sc[nt][2] = (!p0 || c0 > g1)     ? NEGBIG : sc[nt][2] * 0.125f;
            sc[nt][3] = (!p1 || c0 + 1 > g1) ? NEGBIG : sc[nt][3] * 0.125f;
        }

        // ---- online softmax (rows g0, g1) ----
        float mx0 = -1e30f, mx1 = -1e30f;
#pragma unroll
        for (int nt = 0; nt < 8; ++nt) {
            mx0 = fmaxf(mx0, fmaxf(sc[nt][0], sc[nt][1]));
            mx1 = fmaxf(mx1, fmaxf(sc[nt][2], sc[nt][3]));
        }
        mx0 = fmaxf(mx0, __shfl_xor_sync(0xffffffffu, mx0, 1));
        mx0 = fmaxf(mx0, __shfl_xor_sync(0xffffffffu, mx0, 2));
        mx1 = fmaxf(mx1, __shfl_xor_sync(0xffffffffu, mx1, 1));
        mx1 = fmaxf(mx1, __shfl_xor_sync(0xffffffffu, mx1, 2));
        float mn0 = fmaxf(m0, mx0), mn1 = fmaxf(m1, mx1);
        float al0 = __expf(m0 - mn0), al1 = __expf(m1 - mn1);
        m0 = mn0; m1 = mn1;
        float sum0 = 0.f, sum1 = 0.f;
#pragma unroll
        for (int nt = 0; nt < 8; ++nt) {
            sc[nt][0] = __expf(sc[nt][0] - mn0);
            sc[nt][1] = __expf(sc[nt][1] - mn0);
            sc[nt][2] = __expf(sc[nt][2] - mn1);
            sc[nt][3] = __expf(sc[nt][3] - mn1);
            sum0 += sc[nt][0] + sc[nt][1];
            sum1 += sc[nt][2] + sc[nt][3];
        }
        sum0 += __shfl_xor_sync(0xffffffffu, sum0, 1);
        sum0 += __shfl_xor_sync(0xffffffffu, sum0, 2);
        sum1 += __shfl_xor_sync(0xffffffffu, sum1, 1);
        sum1 += __shfl_xor_sync(0xffffffffu, sum1, 2);
        l0 = l0 * al0 + sum0;
        l1 = l1 * al1 + sum1;
#pragma unroll
        for (int nt = 0; nt < 8; ++nt) {
            oacc[nt][0] *= al0; oacc[nt][1] *= al0;
            oacc[nt][2] *= al1; oacc[nt][3] *= al1;
        }

        // ---- O += P V (fp16, P exact 2-term); V trans pairs (r[2*dh], r[2*dh+1]) ----
#pragma unroll
        for (int ks2 = 0; ks2 < 4; ++ks2) {
            uint32_t ph[4], pl[4];
            split2h(sc[2 * ks2][0],     sc[2 * ks2][1],     ph[0], pl[0]);
            split2h(sc[2 * ks2][2],     sc[2 * ks2][3],     ph[1], pl[1]);
            split2h(sc[2 * ks2 + 1][0], sc[2 * ks2 + 1][1], ph[2], pl[2]);
            split2h(sc[2 * ks2 + 1][2], sc[2 * ks2 + 1][3], ph[3], pl[3]);
#pragma unroll
            for (int dn = 0; dn < 4; ++dn) {
                uint32_t vh4[4];
                uint32_t voff = (uint32_t)((ks2 * 16 + vrow) * 144 + dn * 32 + vcol);
                ldm4t(vh4[0], vh4[1], vh4[2], vh4[3], vh_b + voff);
#pragma unroll
                for (int dh = 0; dh < 2; ++dh) {
                    float* o = oacc[dn * 2 + dh];
                    mma_f16(o, ph, vh4[2 * dh], vh4[2 * dh + 1]);
                    mma_f16(o, pl, vh4[2 * dh], vh4[2 * dh + 1]);
                }
            }
        }
        __syncthreads();
    }

    // ---- epilogue: ctx rounded fp16 (single term) ----
    const float i0 = 1.f / l0, i1 = 1.f / l1;
    const size_t r0o = (size_t)(b * SQ + g0) * DM + h * DH;
    const size_t r1o = (size_t)(b * SQ + g1) * DM + h * DH;
#pragma unroll
    for (int nt = 0; nt < 8; ++nt) {
        int cb = (nt >> 1) * 16 + (nt & 1) * 8 + (lane & 3) * 2;
        *(uint32_t*)&g_ch[r0o + cb] = pack2h(oacc[nt][0] * i0, oacc[nt][1] * i0);
        *(uint32_t*)&g_ch[r1o + cb] = pack2h(oacc[nt][2] * i1, oacc[nt][3] * i1);
    }
}

// ---------------- launch ----------------
extern "C" void kernel_launch(void* const* d_in, const int* in_sizes, int n_in,
                              void* d_out, int out_size)
{
    const float* x     = (const float*)d_in[0];
    const int*   amask = (const int*)  d_in[1];
    const float* Wqkv  = (const float*)d_in[2];
    const float* bqkv  = (const float*)d_in[3];
    const float* Aqkv  = (const float*)d_in[4];
    const float* Bqkv  = (const float*)d_in[5];
    const float* Wproj = (const float*)d_in[6];
    const float* bproj = (const float*)d_in[7];
    const float* Aproj = (const float*)d_in[8];
    const float* Bproj = (const float*)d_in[9];
    float* out = (float*)d_out;

    __half *qkvh, *qkvl, *xh, *whT, *phT, *ch;
    cudaGetSymbolAddress((void**)&qkvh, g_qkvh);
    cudaGetSymbolAddress((void**)&qkvl, g_qkvl);
    cudaGetSymbolAddress((void**)&xh,   g_xh);
    cudaGetSymbolAddress((void**)&whT,  g_whT);
    cudaGetSymbolAddress((void**)&phT,  g_phT);
    cudaGetSymbolAddress((void**)&ch,   g_ch);

    cudaFuncSetAttribute(mma_gemm_kernel, cudaFuncAttributeMaxDynamicSharedMemorySize, GSMEM);
    cudaFuncSetAttribute(flash_mma_kernel, cudaFuncAttributeMaxDynamicSharedMemorySize, FL_SMEM);

    // prep
    round_kernel<<<(MR * DM + 255) / 256, 256>>>(x, xh, MR * DM);
    fold_round_T_kernel<<<dim3(N3 / 32, DM / 32), 256>>>(Wqkv,  Aqkv,  Bqkv,  whT, N3, DM);
    fold_round_T_kernel<<<dim3(DM / 32, DM / 32), 256>>>(Wproj, Aproj, Bproj, phT, DM, DM);

    // qkv = x @ W_eff + bias  -> fp16 (hi for all; lo only for Q third)
    mma_gemm_kernel<<<dim3(N3 / 256, MR / 128), 256, GSMEM>>>(
        xh, whT, bqkv, nullptr, qkvh, qkvl, DM, N3, 1);

    // flash attention -> ctx fp16
    flash_mma_kernel<<<dim3(SQ / 128, NH, BB), 256, FL_SMEM>>>(amask);

    // out = ctx @ C_eff + bias (fp32 out)
    mma_gemm_kernel<<<dim3(DM / 256, MR / 128), 256, GSMEM>>>(
        ch, phT, bproj, out, nullptr, nullptr, DM, DM, 0);
}

// round 10
// speedup vs baseline: 5.7714x; 1.1703x over previous
#include <cuda_runtime.h>
#include <cuda_bf16.h>
#include <cuda_fp16.h>
#include <cstdint>

#define DM   1024
#define NH   16
#define DH   64
#define SQ   2048
#define BB   2
#define MR   (BB*SQ)      // 4096 token rows
#define N3   (3*DM)       // 3072
#define RANK 8
#define NEGBIG (-1.25e8f) // -1e9 / sqrt(64)

// ---------------- scratch (static __device__, no allocations) ----------------
__device__ __half g_qkvh[(size_t)MR * N3];   // qkv fp16
__device__ __half g_xh  [(size_t)MR * DM];   // x rounded fp16
__device__ __half g_whT [(size_t)N3 * DM];   // W_qkv^T fp16 (K contiguous)
__device__ __half g_phT [(size_t)DM * DM];   // c_proj^T fp16
__device__ __half g_ch  [(size_t)MR * DM];   // ctx rounded fp16

// ============================ helpers ============================
__device__ __forceinline__ uint32_t smem_u32(const void* p) {
    uint32_t a;
    asm("{ .reg .u64 t; cvta.to.shared.u64 t, %1; cvt.u32.u64 %0, t; }" : "=r"(a) : "l"(p));
    return a;
}
__device__ __forceinline__ void cp16(uint32_t s, const void* g) {
    asm volatile("cp.async.cg.shared.global [%0], [%1], 16;" :: "r"(s), "l"(g));
}
#define CP_COMMIT() asm volatile("cp.async.commit_group;" ::: "memory")

__device__ __forceinline__ void ldm4(uint32_t& r0, uint32_t& r1, uint32_t& r2, uint32_t& r3,
                                     uint32_t addr) {
    asm volatile("ldmatrix.sync.aligned.m8n8.x4.shared.b16 {%0,%1,%2,%3}, [%4];"
                 : "=r"(r0), "=r"(r1), "=r"(r2), "=r"(r3) : "r"(addr));
}
__device__ __forceinline__ void ldm4t(uint32_t& r0, uint32_t& r1, uint32_t& r2, uint32_t& r3,
                                      uint32_t addr) {
    asm volatile("ldmatrix.sync.aligned.m8n8.x4.trans.shared.b16 {%0,%1,%2,%3}, [%4];"
                 : "=r"(r0), "=r"(r1), "=r"(r2), "=r"(r3) : "r"(addr));
}
__device__ __forceinline__ void mma_f16(float* d, const uint32_t* a, uint32_t b0, uint32_t b1) {
    asm volatile("mma.sync.aligned.m16n8k16.row.col.f32.f16.f16.f32 "
                 "{%0,%1,%2,%3}, {%4,%5,%6,%7}, {%8,%9}, {%0,%1,%2,%3};"
                 : "+f"(d[0]), "+f"(d[1]), "+f"(d[2]), "+f"(d[3])
                 : "r"(a[0]), "r"(a[1]), "r"(a[2]), "r"(a[3]), "r"(b0), "r"(b1));
}
__device__ __forceinline__ uint32_t pack2h(float x, float y) {
    __half2 h2; h2.x = __float2half_rn(x); h2.y = __float2half_rn(y);
    return *(uint32_t*)&h2;
}

// ================== prep: round fp32 -> fp16 ==================
__global__ void round_kernel(const float* __restrict__ in, __half* __restrict__ h, int n)
{
    int i = blockIdx.x * 256 + threadIdx.x;
    if (i >= n) return;
    h[i] = __float2half_rn(in[i]);
}

// ====== prep: fold LoRA, round to fp16, transpose (K-contig rows) ======
__global__ __launch_bounds__(256) void fold_round_T_kernel(
    const float* __restrict__ W, const float* __restrict__ A, const float* __restrict__ Bm,
    __half* __restrict__ hT, int N, int K)
{
    __shared__ float sv[32][33];
    const int k0 = blockIdx.y * 32, n0 = blockIdx.x * 32;
    const int r = threadIdx.x >> 5, c = threadIdx.x & 31;
#pragma unroll
    for (int i = 0; i < 4; ++i) {
        int k = k0 + i * 8 + r, n = n0 + c;
        float s = 0.f;
#pragma unroll
        for (int rr = 0; rr < RANK; ++rr)
            s = fmaf(A[k * RANK + rr], Bm[rr * N + n], s);
        sv[i * 8 + r][c] = W[(size_t)k * N + n] + 2.0f * s;
    }
    __syncthreads();
#pragma unroll
    for (int i = 0; i < 4; ++i) {
        int n = n0 + i * 8 + r, k = k0 + c;
        hT[(size_t)n * K + k] = __float2half_rn(sv[c][i * 8 + r]);
    }
}

// ========== mma.sync fp16 GEMM: C = A @ B^T + bias ==========
// CTA tile 128(M) x 256(N), 8 warps (2x4), warp tile 64x64. BK=32, 4-stage cp.async ring.
#define BK 32
#define AST 40
#define TILE_A (128 * AST)            // 5120 halves
#define TILE_B (256 * AST)            // 10240 halves
#define STAGE_ELT (TILE_A + TILE_B)   // 15360 halves = 30720 B
#define NSTG 4
#define GSMEM (NSTG * STAGE_ELT * 2)  // 122880 B

__global__ __launch_bounds__(256) void mma_gemm_kernel(
    const __half* __restrict__ A, const __half* __restrict__ B,
    const float* __restrict__ bias, float* __restrict__ C,
    __half* __restrict__ Ch, int K, int N, int mode)
{
    extern __shared__ __half dsm[];
    const uint32_t sbase = smem_u32(dsm);

    const int tid = threadIdx.x, wid = tid >> 5, lane = tid & 31;
    const int row0 = blockIdx.y * 128, col0 = blockIdx.x * 256;
    const int wm = (wid >> 2) * 64, wn = (wid & 3) * 64;

    float acc[4][8][4] = {};

    const int a_row_l = wm + (lane & 15);
    const int a_k_l   = (lane >> 4) * 8;
    const int b_n_l   = wn + ((lane >> 3) & 1) * 8 + (lane & 7);
    const int b_k_l   = (lane >> 4) * 8;

    const int iters = K / BK;

    auto load_stage = [&](int s, int k0) {
        const uint32_t sb = sbase + s * STAGE_ELT * 2;
#pragma unroll
        for (int t = 0; t < 6; ++t) {
            int idx = tid + t * 256;
            if (idx < 512) {
                int r = idx >> 2, kk = (idx & 3) * 8;
                cp16(sb + (r * AST + kk) * 2, A + (size_t)(row0 + r) * K + k0 + kk);
            } else {
                int i2 = idx - 512;
                int r = i2 >> 2, kk = (i2 & 3) * 8;
                cp16(sb + (TILE_A + r * AST + kk) * 2, B + (size_t)(col0 + r) * K + k0 + kk);
            }
        }
    };

    load_stage(0, 0); CP_COMMIT();
    load_stage(1, BK); CP_COMMIT();
    load_stage(2, 2 * BK); CP_COMMIT();

    for (int it = 0; it < iters; ++it) {
        asm volatile("cp.async.wait_group 2;" ::: "memory");
        __syncthreads();
        if (it + 3 < iters) load_stage((it + 3) & (NSTG - 1), (it + 3) * BK);
        CP_COMMIT();   // unconditional: pending-group count invariant (no tail race)

        const uint32_t sb = sbase + (it & (NSTG - 1)) * STAGE_ELT * 2;
        const uint32_t bA = sb;
        const uint32_t bB = sb + TILE_A * 2;

#pragma unroll
        for (int ks = 0; ks < 2; ++ks) {
            uint32_t bh[4][4];
#pragma unroll
            for (int np = 0; np < 4; ++np) {
                uint32_t off = (uint32_t)((b_n_l + np * 16) * AST + ks * 16 + b_k_l) * 2;
                ldm4(bh[np][0], bh[np][1], bh[np][2], bh[np][3], bB + off);
            }
#pragma unroll
            for (int mt = 0; mt < 4; ++mt) {
                uint32_t aoff = (uint32_t)((a_row_l + mt * 16) * AST + ks * 16 + a_k_l) * 2;
                uint32_t ah[4];
                ldm4(ah[0], ah[1], ah[2], ah[3], bA + aoff);
#pragma unroll
                for (int nt = 0; nt < 8; ++nt) {
                    const int np = nt >> 1, hh = nt & 1;
                    mma_f16(acc[mt][nt], ah, bh[np][hh], bh[np][2 + hh]);
                }
            }
        }
    }

#pragma unroll
    for (int mt = 0; mt < 4; ++mt) {
#pragma unroll
        for (int nt = 0; nt < 8; ++nt) {
            int rr = row0 + wm + mt * 16 + (lane >> 2);
            int cc = col0 + wn + nt * 8 + (lane & 3) * 2;
            float bx = bias[cc], by = bias[cc + 1];
            float v0 = acc[mt][nt][0] + bx, v1 = acc[mt][nt][1] + by;
            float v2 = acc[mt][nt][2] + bx, v3 = acc[mt][nt][3] + by;
            if (mode == 0) {
                *(float2*)&C[(size_t)rr * N + cc]       = make_float2(v0, v1);
                *(float2*)&C[(size_t)(rr + 8) * N + cc] = make_float2(v2, v3);
            } else {
                *(uint32_t*)&Ch[(size_t)rr * N + cc]       = pack2h(v0, v1);
                *(uint32_t*)&Ch[(size_t)(rr + 8) * N + cc] = pack2h(v2, v3);
            }
        }
    }
}

// ============== flash attention, mma.sync fp16 1-term, BM=128 BN=64 ==============
// Q, K, V, P all rounded fp16. S: 1 mma, PV: 1 mma per fragment position.
#define FKST 72
#define Q_BYTES (128*FKST*2)               // 18432
#define KV_BYTES (64*FKST*2)               // 9216
#define STG_BYTES (2*KV_BYTES)             // 18432 (K + V)
#define MSK_OFF (Q_BYTES + 2*STG_BYTES)    // 55296
#define FL_SMEM (MSK_OFF + 512)

__global__ __launch_bounds__(256) void flash_mma_kernel(const int* __restrict__ amask)
{
    extern __shared__ char fsm[];
    const uint32_t sb = smem_u32(fsm);
    int* mskp = (int*)(fsm + MSK_OFF);

    const int qt = (gridDim.x - 1) - blockIdx.x;   // heavy tiles first
    const int h = blockIdx.y, b = blockIdx.z;
    const int tid = threadIdx.x, wid = tid >> 5, lane = tid & 31;
    const int q0 = qt * 128, wrow = wid * 16;

    auto load_q = [&]() {
#pragma unroll
        for (int t = 0; t < 4; ++t) {
            int idx = tid + t * 256;             // 0..1023
            int r = idx >> 3, ch = idx & 7;
            const __half* g = g_qkvh
                + (size_t)(b * SQ + q0 + r) * N3 + h * DH + ch * 8;
            cp16(sb + r * 144 + ch * 16, g);
        }
    };
    auto load_kv = [&](int s, int kb) {
        const uint32_t base = sb + Q_BYTES + s * STG_BYTES;
#pragma unroll
        for (int t = 0; t < 4; ++t) {
            int idx = tid + t * 256;
            int a = idx >> 9, c = idx & 511, r = c >> 3, ch = c & 7;
            const __half* g = g_qkvh
                + (size_t)(b * SQ + kb + r) * N3 + (a ? 2 * DM : DM) + h * DH + ch * 8;
            cp16(base + a * KV_BYTES + r * 144 + ch * 16, g);
        }
        if (tid < 64) mskp[s * 64 + tid] = amask[b * SQ + kb + tid];
    };

    load_q();
    load_kv(0, 0);
    CP_COMMIT();

    const int ktmax = 2 * qt + 1;
    float m0 = -1e30f, m1 = -1e30f, l0 = 0.f, l1 = 0.f;
    float oacc[8][4] = {};
    uint32_t qh[4][4];

    const int arow = wrow + (lane & 15), ak2 = (lane >> 4) * 16;
    const int brow = ((lane >> 3) & 1) * 8 + (lane & 7), bk2 = (lane >> 4) * 16;
    const int vrow = ((lane >> 3) & 1) * 8 + (lane & 7);
    const int vcol = ((lane >> 4) & 1) * 16;
    const int g0 = q0 + wrow + (lane >> 2), g1 = g0 + 8;

    for (int kt = 0; kt <= ktmax; ++kt) {
        if (kt < ktmax) {
            load_kv((kt + 1) & 1, (kt + 1) * 64);
            CP_COMMIT();
            asm volatile("cp.async.wait_group 1;" ::: "memory");
        } else {
            asm volatile("cp.async.wait_group 0;" ::: "memory");
        }
        __syncthreads();

        if (kt == 0) {
#pragma unroll
            for (int ks = 0; ks < 4; ++ks) {
                uint32_t off = (uint32_t)(arow * 144 + ks * 32 + ak2);
                ldm4(qh[ks][0], qh[ks][1], qh[ks][2], qh[ks][3], sb + off);
            }
        }

        const uint32_t kh_b = sb + Q_BYTES + (kt & 1) * STG_BYTES;
        const uint32_t vh_b = kh_b + KV_BYTES;
        const int* msk = mskp + (kt & 1) * 64;
        const int kb = kt * 64;

        // ---- S = Q K^T (fp16 1-term) ----
        float sc[8][4] = {};
#pragma unroll
        for (int ks = 0; ks < 4; ++ks) {
#pragma unroll
            for (int np = 0; np < 4; ++np) {
                uint32_t kh4[4];
                uint32_t off = (uint32_t)((np * 16 + brow) * 144 + ks * 32 + bk2);
                ldm4(kh4[0], kh4[1], kh4[2], kh4[3], kh_b + off);
#pragma unroll
                for (int hh = 0; hh < 2; ++hh) {
                    mma_f16(sc[np * 2 + hh], qh[ks], kh4[hh], kh4[2 + hh]);
                }
            }
        }

        // ---- mask (causal + pad) then scale ----
#pragma unroll
        for (int nt = 0; nt < 8; ++nt) {
            int cb = (nt >> 1) * 16 + (nt & 1) * 8 + (lane & 3) * 2;
            int c0 = kb + cb;
            bool p0 = msk[cb] != 0, p1 = msk[cb + 1] != 0;
            sc[nt][0] = (!p0 || c0 > g0)     ? NEGBIG : sc[nt][0] * 0.125f;
            sc[nt][1] = (!p1 || c0 + 1 > g0) ? NEGBIG : sc[nt][1] * 0.125f;
            sc[nt][2] = (!p0 || c0 > g1)     ? NEGBIG : sc[nt][2] * 0.125f;
            sc[nt][3] = (!p1 || c0 + 1 > g1) ? NEGBIG : sc[nt][3] * 0.125f;
        }

        // ---- online softmax (rows g0, g1) ----
        float mx0 = -1e30f, mx1 = -1e30f;
#pragma unroll
        for (int nt = 0; nt < 8; ++nt) {
            mx0 = fmaxf(mx0, fmaxf(sc[nt][0], sc[nt][1]));
            mx1 = fmaxf(mx1, fmaxf(sc[nt][2], sc[nt][3]));
        }
        mx0 = fmaxf(mx0, __shfl_xor_sync(0xffffffffu, mx0, 1));
        mx0 = fmaxf(mx0, __shfl_xor_sync(0xffffffffu, mx0, 2));
        mx1 = fmaxf(mx1, __shfl_xor_sync(0xffffffffu, mx1, 1));
        mx1 = fmaxf(mx1, __shfl_xor_sync(0xffffffffu, mx1, 2));
        float mn0 = fmaxf(m0, mx0), mn1 = fmaxf(m1, mx1);
        float al0 = __expf(m0 - mn0), al1 = __expf(m1 - mn1);
        m0 = mn0; m1 = mn1;
        float sum0 = 0.f, sum1 = 0.f;
#pragma unroll
        for (int nt = 0; nt < 8; ++nt) {
            sc[nt][0] = __expf(sc[nt][0] - mn0);
            sc[nt][1] = __expf(sc[nt][1] - mn0);
            sc[nt][2] = __expf(sc[nt][2] - mn1);
            sc[nt][3] = __expf(sc[nt][3] - mn1);
            sum0 += sc[nt][0] + sc[nt][1];
            sum1 += sc[nt][2] + sc[nt][3];
        }
        sum0 += __shfl_xor_sync(0xffffffffu, sum0, 1);
        sum0 += __shfl_xor_sync(0xffffffffu, sum0, 2);
        sum1 += __shfl_xor_sync(0xffffffffu, sum1, 1);
        sum1 += __shfl_xor_sync(0xffffffffu, sum1, 2);
        l0 = l0 * al0 + sum0;
        l1 = l1 * al1 + sum1;
#pragma unroll
        for (int nt = 0; nt < 8; ++nt) {
            oacc[nt][0] *= al0; oacc[nt][1] *= al0;
            oacc[nt][2] *= al1; oacc[nt][3] *= al1;
        }

        // ---- O += P V (fp16 1-term); V trans pairs (r[2*dh], r[2*dh+1]) ----
#pragma unroll
        for (int ks2 = 0; ks2 < 4; ++ks2) {
            uint32_t ph[4];
            ph[0] = pack2h(sc[2 * ks2][0],     sc[2 * ks2][1]);
            ph[1] = pack2h(sc[2 * ks2][2],     sc[2 * ks2][3]);
            ph[2] = pack2h(sc[2 * ks2 + 1][0], sc[2 * ks2 + 1][1]);
            ph[3] = pack2h(sc[2 * ks2 + 1][2], sc[2 * ks2 + 1][3]);
#pragma unroll
            for (int dn = 0; dn < 4; ++dn) {
                uint32_t vh4[4];
                uint32_t voff = (uint32_t)((ks2 * 16 + vrow) * 144 + dn * 32 + vcol);
                ldm4t(vh4[0], vh4[1], vh4[2], vh4[3], vh_b + voff);
#pragma unroll
                for (int dh = 0; dh < 2; ++dh) {
                    mma_f16(oacc[dn * 2 + dh], ph, vh4[2 * dh], vh4[2 * dh + 1]);
                }
            }
        }
        __syncthreads();
    }

    // ---- epilogue: ctx rounded fp16 ----
    const float i0 = 1.f / l0, i1 = 1.f / l1;
    const size_t r0o = (size_t)(b * SQ + g0) * DM + h * DH;
    const size_t r1o = (size_t)(b * SQ + g1) * DM + h * DH;
#pragma unroll
    for (int nt = 0; nt < 8; ++nt) {
        int cb = (nt >> 1) * 16 + (nt & 1) * 8 + (lane & 3) * 2;
        *(uint32_t*)&g_ch[r0o + cb] = pack2h(oacc[nt][0] * i0, oacc[nt][1] * i0);
        *(uint32_t*)&g_ch[r1o + cb] = pack2h(oacc[nt][2] * i1, oacc[nt][3] * i1);
    }
}

// ---------------- launch ----------------
extern "C" void kernel_launch(void* const* d_in, const int* in_sizes, int n_in,
                              void* d_out, int out_size)
{
    const float* x     = (const float*)d_in[0];
    const int*   amask = (const int*)  d_in[1];
    const float* Wqkv  = (const float*)d_in[2];
    const float* bqkv  = (const float*)d_in[3];
    const float* Aqkv  = (const float*)d_in[4];
    const float* Bqkv  = (const float*)d_in[5];
    const float* Wproj = (const float*)d_in[6];
    const float* bproj = (const float*)d_in[7];
    const float* Aproj = (const float*)d_in[8];
    const float* Bproj = (const float*)d_in[9];
    float* out = (float*)d_out;

    __half *qkvh, *xh, *whT, *phT, *ch;
    cudaGetSymbolAddress((void**)&qkvh, g_qkvh);
    cudaGetSymbolAddress((void**)&xh,   g_xh);
    cudaGetSymbolAddress((void**)&whT,  g_whT);
    cudaGetSymbolAddress((void**)&phT,  g_phT);
    cudaGetSymbolAddress((void**)&ch,   g_ch);

    cudaFuncSetAttribute(mma_gemm_kernel, cudaFuncAttributeMaxDynamicSharedMemorySize, GSMEM);
    cudaFuncSetAttribute(flash_mma_kernel, cudaFuncAttributeMaxDynamicSharedMemorySize, FL_SMEM);

    // prep
    round_kernel<<<(MR * DM + 255) / 256, 256>>>(x, xh, MR * DM);
    fold_round_T_kernel<<<dim3(N3 / 32, DM / 32), 256>>>(Wqkv,  Aqkv,  Bqkv,  whT, N3, DM);
    fold_round_T_kernel<<<dim3(DM / 32, DM / 32), 256>>>(Wproj, Aproj, Bproj, phT, DM, DM);

    // qkv = x @ W_eff + bias  -> fp16
    mma_gemm_kernel<<<dim3(N3 / 256, MR / 128), 256, GSMEM>>>(
        xh, whT, bqkv, nullptr, qkvh, DM, N3, 1);

    // flash attention -> ctx fp16
    flash_mma_kernel<<<dim3(SQ / 128, NH, BB), 256, FL_SMEM>>>(amask);

    // out = ctx @ C_eff + bias (fp32 out)
    mma_gemm_kernel<<<dim3(DM / 256, MR / 128), 256, GSMEM>>>(
        ch, phT, bproj, out, nullptr, DM, DM, 0);
}

// round 11
// speedup vs baseline: 6.0845x; 1.0542x over previous
#include <cuda_runtime.h>
#include <cuda_bf16.h>
#include <cuda_fp16.h>
#include <cstdint>

#define DM   1024
#define NH   16
#define DH   64
#define SQ   2048
#define BB   2
#define MR   (BB*SQ)      // 4096 token rows
#define N3   (3*DM)       // 3072
#define RANK 8
#define NEGBIG (-1.25e8f) // -1e9 / sqrt(64)

// ---------------- scratch (static __device__, no allocations) ----------------
__device__ __half g_qkvh[(size_t)MR * N3];   // qkv fp16 (Q pre-scaled by 1/8)
__device__ __half g_xh  [(size_t)MR * DM];   // x rounded fp16
__device__ __half g_whT [(size_t)N3 * DM];   // W_qkv^T fp16 (K contiguous)
__device__ __half g_phT [(size_t)DM * DM];   // c_proj^T fp16
__device__ __half g_ch  [(size_t)MR * DM];   // ctx rounded fp16

// ============================ helpers ============================
__device__ __forceinline__ uint32_t smem_u32(const void* p) {
    uint32_t a;
    asm("{ .reg .u64 t; cvta.to.shared.u64 t, %1; cvt.u32.u64 %0, t; }" : "=r"(a) : "l"(p));
    return a;
}
__device__ __forceinline__ void cp16(uint32_t s, const void* g) {
    asm volatile("cp.async.cg.shared.global [%0], [%1], 16;" :: "r"(s), "l"(g));
}
#define CP_COMMIT() asm volatile("cp.async.commit_group;" ::: "memory")

__device__ __forceinline__ void ldm4(uint32_t& r0, uint32_t& r1, uint32_t& r2, uint32_t& r3,
                                     uint32_t addr) {
    asm volatile("ldmatrix.sync.aligned.m8n8.x4.shared.b16 {%0,%1,%2,%3}, [%4];"
                 : "=r"(r0), "=r"(r1), "=r"(r2), "=r"(r3) : "r"(addr));
}
__device__ __forceinline__ void ldm4t(uint32_t& r0, uint32_t& r1, uint32_t& r2, uint32_t& r3,
                                      uint32_t addr) {
    asm volatile("ldmatrix.sync.aligned.m8n8.x4.trans.shared.b16 {%0,%1,%2,%3}, [%4];"
                 : "=r"(r0), "=r"(r1), "=r"(r2), "=r"(r3) : "r"(addr));
}
__device__ __forceinline__ void mma_f16(float* d, const uint32_t* a, uint32_t b0, uint32_t b1) {
    asm volatile("mma.sync.aligned.m16n8k16.row.col.f32.f16.f16.f32 "
                 "{%0,%1,%2,%3}, {%4,%5,%6,%7}, {%8,%9}, {%0,%1,%2,%3};"
                 : "+f"(d[0]), "+f"(d[1]), "+f"(d[2]), "+f"(d[3])
                 : "r"(a[0]), "r"(a[1]), "r"(a[2]), "r"(a[3]), "r"(b0), "r"(b1));
}
__device__ __forceinline__ uint32_t pack2h(float x, float y) {
    __half2 h2; h2.x = __float2half_rn(x); h2.y = __float2half_rn(y);
    return *(uint32_t*)&h2;
}

// ================== prep: round fp32 -> fp16 ==================
__global__ void round_kernel(const float* __restrict__ in, __half* __restrict__ h, int n)
{
    int i = blockIdx.x * 256 + threadIdx.x;
    if (i >= n) return;
    h[i] = __float2half_rn(in[i]);
}

// ====== prep: fold LoRA, round to fp16, transpose (K-contig rows) ======
__global__ __launch_bounds__(256) void fold_round_T_kernel(
    const float* __restrict__ W, const float* __restrict__ A, const float* __restrict__ Bm,
    __half* __restrict__ hT, int N, int K)
{
    __shared__ float sv[32][33];
    const int k0 = blockIdx.y * 32, n0 = blockIdx.x * 32;
    const int r = threadIdx.x >> 5, c = threadIdx.x & 31;
#pragma unroll
    for (int i = 0; i < 4; ++i) {
        int k = k0 + i * 8 + r, n = n0 + c;
        float s = 0.f;
#pragma unroll
        for (int rr = 0; rr < RANK; ++rr)
            s = fmaf(A[k * RANK + rr], Bm[rr * N + n], s);
        sv[i * 8 + r][c] = W[(size_t)k * N + n] + 2.0f * s;
    }
    __syncthreads();
#pragma unroll
    for (int i = 0; i < 4; ++i) {
        int n = n0 + i * 8 + r, k = k0 + c;
        hT[(size_t)n * K + k] = __float2half_rn(sv[c][i * 8 + r]);
    }
}

// ========== mma.sync fp16 GEMM: C = A @ B^T + bias ==========
// CTA tile 128x128, 4 warps (2x2), warp tile 64x64. BK=32, 3-stage cp.async ring.
// 128 threads, ~170 regs -> 3 CTAs/SM (12 warps, 3/SMSP).
#define BK 32
#define AST 40
#define TILE_T (128 * AST)            // 5120 halves per tile (A or B)
#define STAGE_ELT (2 * TILE_T)        // 10240 halves = 20480 B
#define NSTG 3
#define GSMEM (NSTG * STAGE_ELT * 2)  // 61440 B

__global__ __launch_bounds__(128, 3) void mma_gemm_kernel(
    const __half* __restrict__ A, const __half* __restrict__ B,
    const float* __restrict__ bias, float* __restrict__ C,
    __half* __restrict__ Ch, int K, int N, int mode)
{
    extern __shared__ __half dsm[];
    const uint32_t sbase = smem_u32(dsm);

    const int tid = threadIdx.x, wid = tid >> 5, lane = tid & 31;
    const int row0 = blockIdx.y * 128, col0 = blockIdx.x * 128;
    const int wm = (wid >> 1) * 64, wn = (wid & 1) * 64;

    float acc[4][8][4] = {};

    const int a_row_l = wm + (lane & 15);
    const int a_k_l   = (lane >> 4) * 8;
    const int b_n_l   = wn + ((lane >> 3) & 1) * 8 + (lane & 7);
    const int b_k_l   = (lane >> 4) * 8;

    const int iters = K / BK;

    // stage loader: A 512 + B 512 chunks of 16B -> 8 per thread (128 threads)
    auto load_stage = [&](int s, int k0) {
        const uint32_t sb = sbase + s * STAGE_ELT * 2;
#pragma unroll
        for (int t = 0; t < 8; ++t) {
            int idx = tid + t * 128;
            if (idx < 512) {
                int r = idx >> 2, kk = (idx & 3) * 8;
                cp16(sb + (r * AST + kk) * 2, A + (size_t)(row0 + r) * K + k0 + kk);
            } else {
                int i2 = idx - 512;
                int r = i2 >> 2, kk = (i2 & 3) * 8;
                cp16(sb + (TILE_T + r * AST + kk) * 2, B + (size_t)(col0 + r) * K + k0 + kk);
            }
        }
    };

    load_stage(0, 0); CP_COMMIT();
    load_stage(1, BK); CP_COMMIT();

    for (int it = 0; it < iters; ++it) {
        asm volatile("cp.async.wait_group 1;" ::: "memory");
        __syncthreads();
        if (it + 2 < iters) load_stage((it + 2) % NSTG, (it + 2) * BK);
        CP_COMMIT();   // unconditional: pending-group count invariant (no tail race)

        const uint32_t sb = sbase + (it % NSTG) * STAGE_ELT * 2;
        const uint32_t bA = sb;
        const uint32_t bB = sb + TILE_T * 2;

#pragma unroll
        for (int ks = 0; ks < 2; ++ks) {
            uint32_t bh[4][4];
#pragma unroll
            for (int np = 0; np < 4; ++np) {
                uint32_t off = (uint32_t)((b_n_l + np * 16) * AST + ks * 16 + b_k_l) * 2;
                ldm4(bh[np][0], bh[np][1], bh[np][2], bh[np][3], bB + off);
            }
#pragma unroll
            for (int mt = 0; mt < 4; ++mt) {
                uint32_t aoff = (uint32_t)((a_row_l + mt * 16) * AST + ks * 16 + a_k_l) * 2;
                uint32_t ah[4];
                ldm4(ah[0], ah[1], ah[2], ah[3], bA + aoff);
#pragma unroll
                for (int nt = 0; nt < 8; ++nt) {
                    const int np = nt >> 1, hh = nt & 1;
                    mma_f16(acc[mt][nt], ah, bh[np][hh], bh[np][2 + hh]);
                }
            }
        }
    }

#pragma unroll
    for (int mt = 0; mt < 4; ++mt) {
#pragma unroll
        for (int nt = 0; nt < 8; ++nt) {
            int rr = row0 + wm + mt * 16 + (lane >> 2);
            int cc = col0 + wn + nt * 8 + (lane & 3) * 2;
            float bx = bias[cc], by = bias[cc + 1];
            float v0 = acc[mt][nt][0] + bx, v1 = acc[mt][nt][1] + by;
            float v2 = acc[mt][nt][2] + bx, v3 = acc[mt][nt][3] + by;
            if (mode == 0) {
                *(float2*)&C[(size_t)rr * N + cc]       = make_float2(v0, v1);
                *(float2*)&C[(size_t)(rr + 8) * N + cc] = make_float2(v2, v3);
            } else {
                // pre-scale Q columns by 1/8 (exact power-of-2): flash skips its scale
                float s = (cc < DM) ? 0.125f : 1.0f;
                *(uint32_t*)&Ch[(size_t)rr * N + cc]       = pack2h(v0 * s, v1 * s);
                *(uint32_t*)&Ch[(size_t)(rr + 8) * N + cc] = pack2h(v2 * s, v3 * s);
            }
        }
    }
}

// ============== flash attention, mma.sync fp16 1-term, BM=128 BN=64 ==============
// Q pre-scaled by 1/8; Q, K, V, P rounded fp16.
#define FKST 72
#define Q_BYTES (128*FKST*2)               // 18432
#define KV_BYTES (64*FKST*2)               // 9216
#define STG_BYTES (2*KV_BYTES)             // 18432 (K + V)
#define MSK_OFF (Q_BYTES + 2*STG_BYTES)    // 55296
#define FL_SMEM (MSK_OFF + 512)

__global__ __launch_bounds__(256) void flash_mma_kernel(const int* __restrict__ amask)
{
    extern __shared__ char fsm[];
    const uint32_t sb = smem_u32(fsm);
    int* mskp = (int*)(fsm + MSK_OFF);

    const int qt = (gridDim.x - 1) - blockIdx.x;   // heavy tiles first
    const int h = blockIdx.y, b = blockIdx.z;
    const int tid = threadIdx.x, wid = tid >> 5, lane = tid & 31;
    const int q0 = qt * 128, wrow = wid * 16;

    auto load_q = [&]() {
#pragma unroll
        for (int t = 0; t < 4; ++t) {
            int idx = tid + t * 256;             // 0..1023
            int r = idx >> 3, ch = idx & 7;
            const __half* g = g_qkvh
                + (size_t)(b * SQ + q0 + r) * N3 + h * DH + ch * 8;
            cp16(sb + r * 144 + ch * 16, g);
        }
    };
    auto load_kv = [&](int s, int kb) {
        const uint32_t base = sb + Q_BYTES + s * STG_BYTES;
#pragma unroll
        for (int t = 0; t < 4; ++t) {
            int idx = tid + t * 256;
            int a = idx >> 9, c = idx & 511, r = c >> 3, ch = c & 7;
            const __half* g = g_qkvh
                + (size_t)(b * SQ + kb + r) * N3 + (a ? 2 * DM : DM) + h * DH + ch * 8;
            cp16(base + a * KV_BYTES + r * 144 + ch * 16, g);
        }
        if (tid < 64) mskp[s * 64 + tid] = amask[b * SQ + kb + tid];
    };

    load_q();
    load_kv(0, 0);
    CP_COMMIT();

    const int ktmax = 2 * qt + 1;
    float m0 = -1e30f, m1 = -1e30f, l0 = 0.f, l1 = 0.f;
    float oacc[8][4] = {};
    uint32_t qh[4][4];

    const int arow = wrow + (lane & 15), ak2 = (lane >> 4) * 16;
    const int brow = ((lane >> 3) & 1) * 8 + (lane & 7), bk2 = (lane >> 4) * 16;
    const int vrow = ((lane >> 3) & 1) * 8 + (lane & 7);
    const int vcol = ((lane >> 4) & 1) * 16;
    const int g0 = q0 + wrow + (lane >> 2), g1 = g0 + 8;

    for (int kt = 0; kt <= ktmax; ++kt) {
        if (kt < ktmax) {
            load_kv((kt + 1) & 1, (kt + 1) * 64);
            CP_COMMIT();
            asm volatile("cp.async.wait_group 1;" ::: "memory");
        } else {
            asm volatile("cp.async.wait_group 0;" ::: "memory");
        }
        __syncthreads();

        if (kt == 0) {
#pragma unroll
            for (int ks = 0; ks < 4; ++ks) {
                uint32_t off = (uint32_t)(arow * 144 + ks * 32 + ak2);
                ldm4(qh[ks][0], qh[ks][1], qh[ks][2], qh[ks][3], sb + off);
            }
        }

        const uint32_t kh_b = sb + Q_BYTES + (kt & 1) * STG_BYTES;
        const uint32_t vh_b = kh_b + KV_BYTES;
        const int* msk = mskp + (kt & 1) * 64;
        const int kb = kt * 64;

        // ---- S = Q K^T (fp16 1-term; Q pre-scaled) ----
        float sc[8][4] = {};
#pragma unroll
        for (int ks = 0; ks < 4; ++ks) {
#pragma unroll
            for (int np = 0; np < 4; ++np) {
                uint32_t kh4[4];
                uint32_t off = (uint32_t)((np * 16 + brow) * 144 + ks * 32 + bk2);
                ldm4(kh4[0], kh4[1], kh4[2], kh4[3], kh_b + off);
#pragma unroll
                for (int hh = 0; hh < 2; ++hh) {
                    mma_f16(sc[np * 2 + hh], qh[ks], kh4[hh], kh4[2 + hh]);
                }
            }
        }

        // ---- mask (causal + pad); scale already folded into Q ----
#pragma unroll
        for (int nt = 0; nt < 8; ++nt) {
            int cb = (nt >> 1) * 16 + (nt & 1) * 8 + (lane & 3) * 2;
            int c0 = kb + cb;
            bool p0 = msk[cb] != 0, p1 = msk[cb + 1] != 0;
            if (!p0 || c0 > g0)     sc[nt][0] = NEGBIG;
            if (!p1 || c0 + 1 > g0) sc[nt][1] = NEGBIG;
            if (!p0 || c0 > g1)     sc[nt][2] = NEGBIG;
            if (!p1 || c0 + 1 > g1) sc[nt][3] = NEGBIG;
        }

        // ---- online softmax (rows g0, g1) ----
        float mx0 = -1e30f, mx1 = -1e30f;
#pragma unroll
        for (int nt = 0; nt < 8; ++nt) {
            mx0 = fmaxf(mx0, fmaxf(sc[nt][0], sc[nt][1]));
            mx1 = fmaxf(mx1, fmaxf(sc[nt][2], sc[nt][3]));
        }
        mx0 = fmaxf(mx0, __shfl_xor_sync(0xffffffffu, mx0, 1));
        mx0 = fmaxf(mx0, __shfl_xor_sync(0xffffffffu, mx0, 2));
        mx1 = fmaxf(mx1, __shfl_xor_sync(0xffffffffu, mx1, 1));
        mx1 = fmaxf(mx1, __shfl_xor_sync(0xffffffffu, mx1, 2));
        float mn0 = fmaxf(m0, mx0), mn1 = fmaxf(m1, mx1);
        float al0 = __expf(m0 - mn0), al1 = __expf(m1 - mn1);
        m0 = mn0; m1 = mn1;
        float sum0 = 0.f, sum1 = 0.f;
#pragma unroll
        for (int nt = 0; nt < 8; ++nt) {
            sc[nt][0] = __expf(sc[nt][0] - mn0);
            sc[nt][1] = __expf(sc[nt][1] - mn0);
            sc[nt][2] = __expf(sc[nt][2] - mn1);
            sc[nt][3] = __expf(sc[nt][3] - mn1);
            sum0 += sc[nt][0] + sc[nt][1];
            sum1 += sc[nt][2] + sc[nt][3];
        }
        sum0 += __shfl_xor_sync(0xffffffffu, sum0, 1);
        sum0 += __shfl_xor_sync(0xffffffffu, sum0, 2);
        sum1 += __shfl_xor_sync(0xffffffffu, sum1, 1);
        sum1 += __shfl_xor_sync(0xffffffffu, sum1, 2);
        l0 = l0 * al0 + sum0;
        l1 = l1 * al1 + sum1;
#pragma unroll
        for (int nt = 0; nt < 8; ++nt) {
            oacc[nt][0] *= al0; oacc[nt][1] *= al0;
            oacc[nt][2] *= al1; oacc[nt][3] *= al1;
        }

        // ---- O += P V (fp16 1-term); V trans pairs (r[2*dh], r[2*dh+1]) ----
#pragma unroll
        for (int ks2 = 0; ks2 < 4; ++ks2) {
            uint32_t ph[4];
            ph[0] = pack2h(sc[2 * ks2][0],     sc[2 * ks2][1]);
            ph[1] = pack2h(sc[2 * ks2][2],     sc[2 * ks2][3]);
            ph[2] = pack2h(sc[2 * ks2 + 1][0], sc[2 * ks2 + 1][1]);
            ph[3] = pack2h(sc[2 * ks2 + 1][2], sc[2 * ks2 + 1][3]);
#pragma unroll
            for (int dn = 0; dn < 4; ++dn) {
                uint32_t vh4[4];
                uint32_t voff = (uint32_t)((ks2 * 16 + vrow) * 144 + dn * 32 + vcol);
                ldm4t(vh4[0], vh4[1], vh4[2], vh4[3], vh_b + voff);
#pragma unroll
                for (int dh = 0; dh < 2; ++dh) {
                    mma_f16(oacc[dn * 2 + dh], ph, vh4[2 * dh], vh4[2 * dh + 1]);
                }
            }
        }
        __syncthreads();
    }

    // ---- epilogue: ctx rounded fp16 ----
    const float i0 = 1.f / l0, i1 = 1.f / l1;
    const size_t r0o = (size_t)(b * SQ + g0) * DM + h * DH;
    const size_t r1o = (size_t)(b * SQ + g1) * DM + h * DH;
#pragma unroll
    for (int nt = 0; nt < 8; ++nt) {
        int cb = (nt >> 1) * 16 + (nt & 1) * 8 + (lane & 3) * 2;
        *(uint32_t*)&g_ch[r0o + cb] = pack2h(oacc[nt][0] * i0, oacc[nt][1] * i0);
        *(uint32_t*)&g_ch[r1o + cb] = pack2h(oacc[nt][2] * i1, oacc[nt][3] * i1);
    }
}

// ---------------- launch ----------------
extern "C" void kernel_launch(void* const* d_in, const int* in_sizes, int n_in,
                              void* d_out, int out_size)
{
    const float* x     = (const float*)d_in[0];
    const int*   amask = (const int*)  d_in[1];
    const float* Wqkv  = (const float*)d_in[2];
    const float* bqkv  = (const float*)d_in[3];
    const float* Aqkv  = (const float*)d_in[4];
    const float* Bqkv  = (const float*)d_in[5];
    const float* Wproj = (const float*)d_in[6];
    const float* bproj = (const float*)d_in[7];
    const float* Aproj = (const float*)d_in[8];
    const float* Bproj = (const float*)d_in[9];
    float* out = (float*)d_out;

    __half *qkvh, *xh, *whT, *phT, *ch;
    cudaGetSymbolAddress((void**)&qkvh, g_qkvh);
    cudaGetSymbolAddress((void**)&xh,   g_xh);
    cudaGetSymbolAddress((void**)&whT,  g_whT);
    cudaGetSymbolAddress((void**)&phT,  g_phT);
    cudaGetSymbolAddress((void**)&ch,   g_ch);

    cudaFuncSetAttribute(mma_gemm_kernel, cudaFuncAttributeMaxDynamicSharedMemorySize, GSMEM);
    cudaFuncSetAttribute(flash_mma_kernel, cudaFuncAttributeMaxDynamicSharedMemorySize, FL_SMEM);

    // prep
    round_kernel<<<(MR * DM + 255) / 256, 256>>>(x, xh, MR * DM);
    fold_round_T_kernel<<<dim3(N3 / 32, DM / 32), 256>>>(Wqkv,  Aqkv,  Bqkv,  whT, N3, DM);
    fold_round_T_kernel<<<dim3(DM / 32, DM / 32), 256>>>(Wproj, Aproj, Bproj, phT, DM, DM);

    // qkv = x @ W_eff + bias  -> fp16 (Q pre-scaled by 1/8)
    mma_gemm_kernel<<<dim3(N3 / 128, MR / 128), 128, GSMEM>>>(
        xh, whT, bqkv, nullptr, qkvh, DM, N3, 1);

    // flash attention -> ctx fp16
    flash_mma_kernel<<<dim3(SQ / 128, NH, BB), 256, FL_SMEM>>>(amask);

    // out = ctx @ C_eff + bias (fp32 out)
    mma_gemm_kernel<<<dim3(DM / 128, MR / 128), 128, GSMEM>>>(
        ch, phT, bproj, out, nullptr, DM, DM, 0);
}